// round 9
// baseline (speedup 1.0000x reference)
#include <cuda_runtime.h>
#include <cuda_bf16.h>
#include <math.h>
#include <stdint.h>

#define BB     4
#define HH_    32
#define WW_    32
#define MM_    16
#define DD     128
#define NN     16384          // H*W*M
#define BN     65536          // B*N
#define D2     256
#define D4     512
#define NHEADS 4
#define HK     32
#define EPSLN  1e-5f
#define CSPLIT 256

// ---------------- scratch (device globals; no allocation allowed) ----------
__device__ __align__(16) float g_n1[BN * DD];
__device__ __align__(16) float g_n2[BN * DD];
__device__ __align__(16) float g_pmax[BB * CSPLIT * DD];
__device__ __align__(16) float g_psum[BB * CSPLIT * DD];
__device__ __align__(16) float g_cmax[BB * DD];
__device__ __align__(16) float g_cinv[BB * DD];
__device__ __align__(16) float g_ctxp[32 * BB * NHEADS * HK * HK];
__device__ __align__(16) float g_ctx[BB * NHEADS * HK * HK];
__device__ __align__(16) float g_rep[BN * D2];
__device__ __align__(16) float g_tx[BN * D2];
__device__ __align__(16) float g_h1[(size_t)BN * D4];
__device__ __align__(16) float g_dwT[27 * D4];
// pre-split bf16 GEMM A operands
__device__ __align__(16) __nv_bfloat16 g_agghi[BN * DD],        g_agglo[BN * DD];
__device__ __align__(16) __nv_bfloat16 g_yhi[BN * D2],          g_ylo[BN * D2];
__device__ __align__(16) __nv_bfloat16 g_axhi[(size_t)BN * D4], g_axlo[(size_t)BN * D4];
// pre-split bf16 weights, [N][K] K-major
__device__ __align__(16) __nv_bfloat16 g_w0hi[D2 * DD], g_w0lo[D2 * DD];   // rep
__device__ __align__(16) __nv_bfloat16 g_w1hi[D4 * D2], g_w1lo[D4 * D2];   // fc1
__device__ __align__(16) __nv_bfloat16 g_w2hi[D2 * D4], g_w2lo[D2 * D4];   // fc2

// ---------------- helpers ---------------------------------------------------
// NOTE: not volatile — dependencies are fully expressed via register
// constraints, letting ptxas interleave independent HMMAs and LDSMs.
__device__ __forceinline__ void mma16816(float* c, const uint32_t* a, const uint32_t* b) {
    asm("mma.sync.aligned.m16n8k16.row.col.f32.bf16.bf16.f32 "
        "{%0,%1,%2,%3}, {%4,%5,%6,%7}, {%8,%9}, {%0,%1,%2,%3};"
        : "+f"(c[0]), "+f"(c[1]), "+f"(c[2]), "+f"(c[3])
        : "r"(a[0]), "r"(a[1]), "r"(a[2]), "r"(a[3]), "r"(b[0]), "r"(b[1]));
}
__device__ __forceinline__ uint32_t smem_u32(const void* p) {
    uint32_t a;
    asm("{ .reg .u64 t; cvta.to.shared.u64 t, %1; cvt.u32.u64 %0, t; }" : "=r"(a) : "l"(p));
    return a;
}
__device__ __forceinline__ void ldsm_x4(uint32_t* r, uint32_t addr) {
    asm volatile("ldmatrix.sync.aligned.m8n8.x4.shared.b16 {%0,%1,%2,%3}, [%4];"
                 : "=r"(r[0]), "=r"(r[1]), "=r"(r[2]), "=r"(r[3]) : "r"(addr));
}
__device__ __forceinline__ void split_bf16(float v, uint16_t& hb, uint16_t& lb) {
    __nv_bfloat16 h = __float2bfloat16(v);
    __nv_bfloat16 l = __float2bfloat16(v - __bfloat162float(h));
    hb = __bfloat16_as_ushort(h);
    lb = __bfloat16_as_ushort(l);
}
// split a float4 and pack into uint2 (4 bf16)
__device__ __forceinline__ void split4(float4 v, uint2& hp, uint2& lp) {
    uint16_t hh[4], ll[4];
    split_bf16(v.x, hh[0], ll[0]);
    split_bf16(v.y, hh[1], ll[1]);
    split_bf16(v.z, hh[2], ll[2]);
    split_bf16(v.w, hh[3], ll[3]);
    hp.x = (uint32_t)hh[0] | ((uint32_t)hh[1] << 16);
    hp.y = (uint32_t)hh[2] | ((uint32_t)hh[3] << 16);
    lp.x = (uint32_t)ll[0] | ((uint32_t)ll[1] << 16);
    lp.y = (uint32_t)ll[2] | ((uint32_t)ll[3] << 16);
}

// ---------------- LayerNorm: one warp per row, float4 ----------------------
template <int MODE>
__global__ void ln_kernel(const float* __restrict__ x,
                          const float* __restrict__ gg,
                          const float* __restrict__ bb) {
    int gw = (blockIdx.x * blockDim.x + threadIdx.x) >> 5;
    int lane = threadIdx.x & 31;
    if (gw >= BN) return;
    float* dst = (MODE == 0) ? g_n1 : g_n2;

    const float4* xr = reinterpret_cast<const float4*>(x) + (size_t)gw * 32;
    float4 v = xr[lane];
    float s = v.x + v.y + v.z + v.w;
    float ss = v.x * v.x + v.y * v.y + v.z * v.z + v.w * v.w;
#pragma unroll
    for (int o = 16; o > 0; o >>= 1) {
        s  += __shfl_xor_sync(0xffffffffu, s, o);
        ss += __shfl_xor_sync(0xffffffffu, ss, o);
    }
    float mean = s * (1.0f / DD);
    float rstd = rsqrtf(ss * (1.0f / DD) - mean * mean + EPSLN);

    float4 gv = reinterpret_cast<const float4*>(gg)[lane];
    float4 bv = reinterpret_cast<const float4*>(bb)[lane];
    float4 r;
    r.x = (v.x - mean) * rstd * gv.x + bv.x;
    r.y = (v.y - mean) * rstd * gv.y + bv.y;
    r.z = (v.z - mean) * rstd * gv.z + bv.z;
    r.w = (v.w - mean) * rstd * gv.w + bv.w;
    reinterpret_cast<float4*>(dst)[(size_t)gw * 32 + lane] = r;
}

// ---------------- key softmax column stats over N (partials) --------------
__global__ void colstats_kernel() {
    int b = blockIdx.x >> 8, sp = blockIdx.x & (CSPLIT - 1);
    int d = threadIdx.x;
    const float* p = g_n2 + ((size_t)b * NN + sp * (NN / CSPLIT)) * DD + d;
    float m = -1e30f, s = 0.f;
    for (int i = 0; i < NN / CSPLIT; i++) {
        float v = p[(size_t)i * DD];
        float nm = fmaxf(m, v);
        s = s * __expf(m - nm) + __expf(v - nm);
        m = nm;
    }
    g_pmax[blockIdx.x * DD + d] = m;
    g_psum[blockIdx.x * DD + d] = s;
}

__global__ void colcombine_kernel() {
    int b = blockIdx.x, d = threadIdx.x;
    float m = -1e30f, s = 0.f;
    for (int sp = 0; sp < CSPLIT; sp++) {
        float pm = g_pmax[(b * CSPLIT + sp) * DD + d];
        float ps = g_psum[(b * CSPLIT + sp) * DD + d];
        float nm = fmaxf(m, pm);
        s = s * __expf(m - nm) + ps * __expf(pm - nm);
        m = nm;
    }
    g_cmax[b * DD + d] = m;
    g_cinv[b * DD + d] = 1.0f / s;
}

// ---------------- context[b,h,k,v] = sum_n key * v   (split-N partials) ---
__global__ void ctx_kernel() {
    int sp = blockIdx.x & 31;
    int h  = (blockIdx.x >> 5) & 3;
    int b  = blockIdx.x >> 7;
    int tid = threadIdx.x;
    int v = tid & 31, k = tid >> 5;

    __shared__ float cm[HK], ci[HK];
    __shared__ float ke[16][HK], vv[16][HK];
    if (tid < HK) {
        cm[tid] = g_cmax[b * DD + h * HK + tid];
        ci[tid] = g_cinv[b * DD + h * HK + tid];
    }
    float acc = 0.f;
    int n0 = sp * 512;
    int tt = tid >> 6, col = tid & 63;
    for (int t0 = 0; t0 < 512; t0 += 16) {
        __syncthreads();
        int n = n0 + t0 + tt;
        size_t base = ((size_t)b * NN + n) * DD + h * HK;
        if (col < HK) ke[tt][col] = __expf(g_n2[base + col] - cm[col]) * ci[col];
        else          vv[tt][col - HK] = g_n1[base + col - HK];
        __syncthreads();
#pragma unroll
        for (int t = 0; t < 16; t++) acc += ke[t][k] * vv[t][v];
    }
    g_ctxp[(size_t)sp * (BB * NHEADS * HK * HK) +
           (((b * NHEADS + h) * HK + k) * HK + v)] = acc;
}

__global__ void ctx_reduce_kernel() {
    int i = blockIdx.x * 1024 + threadIdx.x;
    float s = 0.f;
    for (int sp = 0; sp < 32; sp++) s += g_ctxp[sp * (BB * NHEADS * HK * HK) + i];
    g_ctx[i] = s;
}

// ---------------- weight re-layouts + bf16 splits ---------------------------
__global__ void prep_weights(const float* __restrict__ rep_w,
                             const float* __restrict__ dw_w,
                             const float* __restrict__ fc1_w,
                             const float* __restrict__ fc2_w) {
    int i = blockIdx.x * 256 + threadIdx.x;
    uint16_t hb, lb;
    if (i < D2 * DD) {                      // rep_w already [N=256][K=128]
        split_bf16(rep_w[i], hb, lb);
        g_w0hi[i] = __ushort_as_bfloat16(hb); g_w0lo[i] = __ushort_as_bfloat16(lb);
    }
    if (i < D4 * D2) {                      // fc1_w [K=256][N=512] -> [n][k]
        int n = i >> 8, k = i & 255;
        split_bf16(fc1_w[k * D4 + n], hb, lb);
        g_w1hi[i] = __ushort_as_bfloat16(hb); g_w1lo[i] = __ushort_as_bfloat16(lb);
    }
    if (i < D2 * D4) {                      // fc2_w [K=512][N=256] -> [n][k]
        int n = i >> 9, k = i & 511;
        split_bf16(fc2_w[k * D2 + n], hb, lb);
        g_w2hi[i] = __ushort_as_bfloat16(hb); g_w2lo[i] = __ushort_as_bfloat16(lb);
    }
    if (i < 27 * D4) {                      // dw_w [c][27] -> [tap][c]
        int c = i / 27, t = i % 27;
        g_dwT[t * D4 + c] = dw_w[i];
    }
}

// ---------------- query softmax + att matvec -> agg (split bf16) ----------
__global__ void attq_kernel() {
    __shared__ float sn2[32][129];
    __shared__ float sctx[NHEADS][HK][HK];
    int b = blockIdx.x >> 9;
    int tok0 = (blockIdx.x & 511) * 32;
    int tid = threadIdx.x;

    for (int i = tid; i < NHEADS * HK * HK; i += 128)
        ((float*)sctx)[i] = g_ctx[b * (NHEADS * HK * HK) + i];
    for (int i = tid; i < 32 * 128; i += 128) {
        int r = i >> 7, c = i & 127;
        sn2[r][c] = g_n2[((size_t)b * NN + tok0 + r) * DD + c];
    }
    __syncthreads();

    int h = tid >> 5, t = tid & 31;
    float q[HK];
    float mx = -1e30f;
#pragma unroll
    for (int k = 0; k < HK; k++) { q[k] = sn2[t][h * HK + k]; mx = fmaxf(mx, q[k]); }
    float sum = 0.f;
#pragma unroll
    for (int k = 0; k < HK; k++) { q[k] = __expf(q[k] - mx); sum += q[k]; }
    float inv = 1.0f / sum;

    float av[HK];
#pragma unroll
    for (int j = 0; j < HK; j++) av[j] = 0.f;
#pragma unroll
    for (int k = 0; k < HK; k++) {
        float qk = q[k] * inv;
#pragma unroll
        for (int j = 0; j < HK; j++) av[j] += qk * sctx[h][k][j];
    }
    __syncthreads();
#pragma unroll
    for (int j = 0; j < HK; j++) sn2[t][h * HK + j] = av[j];
    __syncthreads();
    // scalar LDS reads (row stride 129 floats is not 16B-aligned)
    for (int i = tid; i < 32 * 32; i += 128) {
        int r = i >> 5, c4 = i & 31;
        float4 v;
        v.x = sn2[r][c4 * 4 + 0];
        v.y = sn2[r][c4 * 4 + 1];
        v.z = sn2[r][c4 * 4 + 2];
        v.w = sn2[r][c4 * 4 + 3];
        uint2 hp, lp;
        split4(v, hp, lp);
        size_t idx = ((size_t)b * NN + tok0 + r) * DD + c4 * 4;
        *reinterpret_cast<uint2*>(&g_agghi[idx]) = hp;
        *reinterpret_cast<uint2*>(&g_agglo[idx]) = lp;
    }
}

// ---------------- HMMA bf16 3-term split GEMM (ldmatrix fragments) ----------
// WHICH 0: agg[65536,128] @ w0[256,128]^T            -> g_rep
// WHICH 1: y  [65536,256] @ w1[512,256]^T            -> g_h1
// WHICH 2: ax [65536,512] @ w2[256,512]^T + b + tx   -> Cout (d_out)
// CTA tile 128x128, BK=32, 8 warps (4m x 2n), warp tile 32x64.
#define LDKP 40                      // padded bf16 k-stride (80B rows: LDSM conflict-free)
#define ATILE (128 * LDKP)           // elems per matrix per stage
#define HSMEM_BYTES (8 * ATILE * 2)  // 4 matrices x 2 stages = 81920 B

template <int WHICH>
__global__ void __launch_bounds__(256) hgemm_kernel(const float* __restrict__ bias,
                                                    float* __restrict__ CoutP) {
    constexpr int K  = (WHICH == 0) ? 128 : (WHICH == 1) ? 256 : 512;
    constexpr int Nc = (WHICH == 1) ? 512 : 256;
    constexpr int CHUNKS = K / 32;

    const __nv_bfloat16* Ah = (WHICH == 0) ? g_agghi : (WHICH == 1) ? g_yhi : g_axhi;
    const __nv_bfloat16* Al = (WHICH == 0) ? g_agglo : (WHICH == 1) ? g_ylo : g_axlo;
    const __nv_bfloat16* Bh = (WHICH == 0) ? g_w0hi : (WHICH == 1) ? g_w1hi : g_w2hi;
    const __nv_bfloat16* Bl = (WHICH == 0) ? g_w0lo : (WHICH == 1) ? g_w1lo : g_w2lo;
    float* C = (WHICH == 0) ? g_rep : (WHICH == 1) ? g_h1 : CoutP;

    extern __shared__ __align__(16) __nv_bfloat16 sm_bf[];
    __nv_bfloat16* sAh = sm_bf;               // [2][ATILE]
    __nv_bfloat16* sAl = sAh + 2 * ATILE;
    __nv_bfloat16* sBh = sAl + 2 * ATILE;
    __nv_bfloat16* sBl = sBh + 2 * ATILE;

    int tid = threadIdx.x, lane = tid & 31, wid = tid >> 5;
    int wm = wid >> 1, wn = wid & 1;
    int m0 = blockIdx.y * 128, n0 = blockIdx.x * 128;
    int g = lane >> 2, t4 = lane & 3;

    int ar_ = tid >> 2, aq_ = tid & 3;  // A loader: row ar_+64i, uint4-col aq_ (8 bf16)
    int bn = tid >> 2, bq = tid & 3;    // B loader: row bn+64i, uint4-col bq

    // ldmatrix per-lane element offsets (in bf16 elems, relative to stage base)
    int a_row = wm * 32 + (lane & 15);
    int a_elem = a_row * LDKP + (lane >> 4) * 8;
    int b_row = wn * 64 + (lane & 7) + ((lane >> 4) << 3);
    int b_elem = b_row * LDKP + ((lane >> 3) & 1) * 8;

    uint32_t sAh_u = smem_u32(sAh), sAl_u = smem_u32(sAl);
    uint32_t sBh_u = smem_u32(sBh), sBl_u = smem_u32(sBl);

    uint4 ahr[2], alr[2], bhr[2], blr[2];
    float acc[2][8][4] = {};

    // ---- prologue: LDG chunk 0
#pragma unroll
    for (int i = 0; i < 2; i++) {
        size_t aoff = (size_t)(m0 + ar_ + 64 * i) * K + aq_ * 8;
        ahr[i] = *reinterpret_cast<const uint4*>(Ah + aoff);
        alr[i] = *reinterpret_cast<const uint4*>(Al + aoff);
        size_t boff = (size_t)(n0 + bn + 64 * i) * K + bq * 8;
        bhr[i] = *reinterpret_cast<const uint4*>(Bh + boff);
        blr[i] = *reinterpret_cast<const uint4*>(Bl + boff);
    }
    // STS stage 0
#pragma unroll
    for (int i = 0; i < 2; i++) {
        int ra = ar_ + 64 * i, rb = bn + 64 * i;
        *reinterpret_cast<uint4*>(sAh + ra * LDKP + aq_ * 8) = ahr[i];
        *reinterpret_cast<uint4*>(sAl + ra * LDKP + aq_ * 8) = alr[i];
        *reinterpret_cast<uint4*>(sBh + rb * LDKP + bq * 8) = bhr[i];
        *reinterpret_cast<uint4*>(sBl + rb * LDKP + bq * 8) = blr[i];
    }
    __syncthreads();

    for (int c = 0; c < CHUNKS; c++) {
        int s = c & 1;
        if (c + 1 < CHUNKS) {  // prefetch next chunk
            int k0 = (c + 1) * 32;
#pragma unroll
            for (int i = 0; i < 2; i++) {
                size_t aoff = (size_t)(m0 + ar_ + 64 * i) * K + k0 + aq_ * 8;
                ahr[i] = *reinterpret_cast<const uint4*>(Ah + aoff);
                alr[i] = *reinterpret_cast<const uint4*>(Al + aoff);
                size_t boff = (size_t)(n0 + bn + 64 * i) * K + k0 + bq * 8;
                bhr[i] = *reinterpret_cast<const uint4*>(Bh + boff);
                blr[i] = *reinterpret_cast<const uint4*>(Bl + boff);
            }
        }
        uint32_t stg = (uint32_t)(s * ATILE * 2);  // stage byte offset

#pragma unroll
        for (int kk = 0; kk < 32; kk += 16) {
            uint32_t ah[2][4], al[2][4], bh[8][2], bl[8][2];
            uint32_t a_base = stg + (uint32_t)(a_elem + kk) * 2;
            uint32_t b_base = stg + (uint32_t)(b_elem + kk) * 2;
#pragma unroll
            for (int mt = 0; mt < 2; mt++) {
                uint32_t off = a_base + (uint32_t)(mt * 16 * LDKP) * 2;
                ldsm_x4(ah[mt], sAh_u + off);
                ldsm_x4(al[mt], sAl_u + off);
            }
#pragma unroll
            for (int p = 0; p < 4; p++) {
                uint32_t off = b_base + (uint32_t)(p * 16 * LDKP) * 2;
                uint32_t th[4], tl[4];
                ldsm_x4(th, sBh_u + off);
                ldsm_x4(tl, sBl_u + off);
                bh[2 * p][0] = th[0]; bh[2 * p][1] = th[1];
                bh[2 * p + 1][0] = th[2]; bh[2 * p + 1][1] = th[3];
                bl[2 * p][0] = tl[0]; bl[2 * p][1] = tl[1];
                bl[2 * p + 1][0] = tl[2]; bl[2 * p + 1][1] = tl[3];
            }
            // term-major order: consecutive MMAs hit 16 DISTINCT accumulators,
            // so same-acc reuse is 16 issues apart (covers HMMA latency).
#pragma unroll
            for (int mt = 0; mt < 2; mt++)
#pragma unroll
                for (int nt = 0; nt < 8; nt++)
                    mma16816(acc[mt][nt], ah[mt], bh[nt]);
#pragma unroll
            for (int mt = 0; mt < 2; mt++)
#pragma unroll
                for (int nt = 0; nt < 8; nt++)
                    mma16816(acc[mt][nt], al[mt], bh[nt]);
#pragma unroll
            for (int mt = 0; mt < 2; mt++)
#pragma unroll
                for (int nt = 0; nt < 8; nt++)
                    mma16816(acc[mt][nt], ah[mt], bl[nt]);
        }

        if (c + 1 < CHUNKS) {  // STS next stage
            int s1 = (c + 1) & 1;
#pragma unroll
            for (int i = 0; i < 2; i++) {
                int ra = ar_ + 64 * i, rb = bn + 64 * i;
                *reinterpret_cast<uint4*>(sAh + s1 * ATILE + ra * LDKP + aq_ * 8) = ahr[i];
                *reinterpret_cast<uint4*>(sAl + s1 * ATILE + ra * LDKP + aq_ * 8) = alr[i];
                *reinterpret_cast<uint4*>(sBh + s1 * ATILE + rb * LDKP + bq * 8) = bhr[i];
                *reinterpret_cast<uint4*>(sBl + s1 * ATILE + rb * LDKP + bq * 8) = blr[i];
            }
        }
        __syncthreads();
    }

    // ---- epilogue
#pragma unroll
    for (int mt = 0; mt < 2; mt++) {
        int r0 = m0 + wm * 32 + mt * 16 + g;
#pragma unroll
        for (int nt = 0; nt < 8; nt++) {
            int ccol = n0 + wn * 64 + nt * 8 + t4 * 2;
            float2 bv = *reinterpret_cast<const float2*>(bias + ccol);
            float2 o0, o1;
            o0.x = acc[mt][nt][0] + bv.x; o0.y = acc[mt][nt][1] + bv.y;
            o1.x = acc[mt][nt][2] + bv.x; o1.y = acc[mt][nt][3] + bv.y;
            if (WHICH == 2) {
                float2 t0 = *reinterpret_cast<const float2*>(&g_tx[(size_t)r0 * Nc + ccol]);
                float2 t1 = *reinterpret_cast<const float2*>(&g_tx[(size_t)(r0 + 8) * Nc + ccol]);
                o0.x += t0.x; o0.y += t0.y; o1.x += t1.x; o1.y += t1.y;
            }
            *reinterpret_cast<float2*>(&C[(size_t)r0 * Nc + ccol]) = o0;
            *reinterpret_cast<float2*>(&C[(size_t)(r0 + 8) * Nc + ccol]) = o1;
        }
    }
}

// ---- tx = LN(rep)+concat(x1,x2) (f32)  AND  y = LN(tx) split bf16 ----------
__global__ void txy_kernel(const float* __restrict__ x1, const float* __restrict__ x2,
                           const float* __restrict__ ag, const float* __restrict__ ab,
                           const float* __restrict__ g2, const float* __restrict__ b2) {
    int gw = (blockIdx.x * blockDim.x + threadIdx.x) >> 5;
    int lane = threadIdx.x & 31;
    if (gw >= BN) return;
    const float4* rr = reinterpret_cast<const float4*>(g_rep) + (size_t)gw * 64;
    float4 v[2];
    float s = 0.f, ss = 0.f;
#pragma unroll
    for (int i = 0; i < 2; i++) {
        v[i] = rr[i * 32 + lane];
        s  += v[i].x + v[i].y + v[i].z + v[i].w;
        ss += v[i].x * v[i].x + v[i].y * v[i].y + v[i].z * v[i].z + v[i].w * v[i].w;
    }
#pragma unroll
    for (int o = 16; o > 0; o >>= 1) {
        s  += __shfl_xor_sync(0xffffffffu, s, o);
        ss += __shfl_xor_sync(0xffffffffu, ss, o);
    }
    float mean = s * (1.0f / D2);
    float rstd = rsqrtf(ss * (1.0f / D2) - mean * mean + EPSLN);

    const float4* g4 = reinterpret_cast<const float4*>(ag);
    const float4* b4 = reinterpret_cast<const float4*>(ab);
    const float4* x14 = reinterpret_cast<const float4*>(x1) + (size_t)gw * 32;
    const float4* x24 = reinterpret_cast<const float4*>(x2) + (size_t)gw * 32;
    float4* txr = reinterpret_cast<float4*>(g_tx) + (size_t)gw * 64;

    float4 tv[2];
    float s2 = 0.f, ss2 = 0.f;
#pragma unroll
    for (int i = 0; i < 2; i++) {
        int c4 = i * 32 + lane;
        float4 gv = g4[c4], bv = b4[c4];
        float4 cat = (i == 0) ? x14[lane] : x24[lane];
        float4 r;
        r.x = (v[i].x - mean) * rstd * gv.x + bv.x + cat.x;
        r.y = (v[i].y - mean) * rstd * gv.y + bv.y + cat.y;
        r.z = (v[i].z - mean) * rstd * gv.z + bv.z + cat.z;
        r.w = (v[i].w - mean) * rstd * gv.w + bv.w + cat.w;
        txr[c4] = r;
        tv[i] = r;
        s2  += r.x + r.y + r.z + r.w;
        ss2 += r.x * r.x + r.y * r.y + r.z * r.z + r.w * r.w;
    }
#pragma unroll
    for (int o = 16; o > 0; o >>= 1) {
        s2  += __shfl_xor_sync(0xffffffffu, s2, o);
        ss2 += __shfl_xor_sync(0xffffffffu, ss2, o);
    }
    float mean2 = s2 * (1.0f / D2);
    float rstd2 = rsqrtf(ss2 * (1.0f / D2) - mean2 * mean2 + EPSLN);

    const float4* g24 = reinterpret_cast<const float4*>(g2);
    const float4* b24 = reinterpret_cast<const float4*>(b2);
#pragma unroll
    for (int i = 0; i < 2; i++) {
        int c4 = i * 32 + lane;
        float4 gv = g24[c4], bv = b24[c4], r;
        r.x = (tv[i].x - mean2) * rstd2 * gv.x + bv.x;
        r.y = (tv[i].y - mean2) * rstd2 * gv.y + bv.y;
        r.z = (tv[i].z - mean2) * rstd2 * gv.z + bv.z;
        r.w = (tv[i].w - mean2) * rstd2 * gv.w + bv.w;
        uint2 hp, lp;
        split4(r, hp, lp);
        size_t idx = (size_t)gw * D2 + c4 * 4;
        *reinterpret_cast<uint2*>(&g_yhi[idx]) = hp;
        *reinterpret_cast<uint2*>(&g_ylo[idx]) = lp;
    }
}

// ---- dwconv + bias + h1, then LN + GELU, write ax split bf16 ---------------
__global__ void dwlngelu_kernel(const float* __restrict__ dwb,
                                const float* __restrict__ mg,
                                const float* __restrict__ mb) {
    __shared__ float red[8];
    int n = blockIdx.x;
    int loc = n & (NN - 1);
    int m_ = loc & 15, w_ = (loc >> 4) & 31, h_ = loc >> 9;
    int tc = threadIdx.x;
    int lane = tc & 31, wrp = tc >> 5;
    const float4* x4 = reinterpret_cast<const float4*>(g_h1);

    float4 acc = x4[(size_t)n * 128 + tc];
    float4 bv = reinterpret_cast<const float4*>(dwb)[tc];
    acc.x += bv.x; acc.y += bv.y; acc.z += bv.z; acc.w += bv.w;

#pragma unroll
    for (int di = -1; di <= 1; di++) {
        int hh = h_ + di;
        if (hh < 0 || hh >= HH_) continue;
#pragma unroll
        for (int dj = -1; dj <= 1; dj++) {
            int ww = w_ + dj;
            if (ww < 0 || ww >= WW_) continue;
#pragma unroll
            for (int dk = -1; dk <= 1; dk++) {
                int mm = m_ + dk;
                if (mm < 0 || mm >= MM_) continue;
                int nn = n + di * (WW_ * MM_) + dj * MM_ + dk;
                float4 xv = x4[(size_t)nn * 128 + tc];
                float4 wt = reinterpret_cast<const float4*>(
                    g_dwT)[((di + 1) * 9 + (dj + 1) * 3 + (dk + 1)) * 128 + tc];
                acc.x += xv.x * wt.x; acc.y += xv.y * wt.y;
                acc.z += xv.z * wt.z; acc.w += xv.w * wt.w;
            }
        }
    }

    // block LN over 512 channels
    float s = acc.x + acc.y + acc.z + acc.w;
    float ss = acc.x * acc.x + acc.y * acc.y + acc.z * acc.z + acc.w * acc.w;
#pragma unroll
    for (int o = 16; o > 0; o >>= 1) {
        s  += __shfl_xor_sync(0xffffffffu, s, o);
        ss += __shfl_xor_sync(0xffffffffu, ss, o);
    }
    if (lane == 0) { red[wrp] = s; red[4 + wrp] = ss; }
    __syncthreads();
    s = red[0] + red[1] + red[2] + red[3];
    ss = red[4] + red[5] + red[6] + red[7];
    float mean = s * (1.0f / D4);
    float rstd = rsqrtf(ss * (1.0f / D4) - mean * mean + EPSLN);

    float4 gv = reinterpret_cast<const float4*>(mg)[tc];
    float4 b2 = reinterpret_cast<const float4*>(mb)[tc];
    float4 r;
    float t;
    t = (acc.x - mean) * rstd * gv.x + b2.x; r.x = t * normcdff(t);
    t = (acc.y - mean) * rstd * gv.y + b2.y; r.y = t * normcdff(t);
    t = (acc.z - mean) * rstd * gv.z + b2.z; r.z = t * normcdff(t);
    t = (acc.w - mean) * rstd * gv.w + b2.w; r.w = t * normcdff(t);

    uint2 hp, lp;
    split4(r, hp, lp);
    size_t idx = (size_t)n * D4 + tc * 4;
    *reinterpret_cast<uint2*>(&g_axhi[idx]) = hp;
    *reinterpret_cast<uint2*>(&g_axlo[idx]) = lp;
}

// ---------------------------------------------------------------------------
extern "C" void kernel_launch(void* const* d_in, const int* in_sizes, int n_in,
                              void* d_out, int out_size) {
    const float* x1    = (const float*)d_in[0];
    const float* x2    = (const float*)d_in[1];
    const float* ln1_g = (const float*)d_in[2];
    const float* ln1_b = (const float*)d_in[3];
    const float* rep_w = (const float*)d_in[4];
    const float* rep_b = (const float*)d_in[5];
    const float* aln_g = (const float*)d_in[6];
    const float* aln_b = (const float*)d_in[7];
    const float* ln2_g = (const float*)d_in[8];
    const float* ln2_b = (const float*)d_in[9];
    const float* fc1_w = (const float*)d_in[10];
    const float* fc1_b = (const float*)d_in[11];
    const float* dw_w  = (const float*)d_in[12];
    const float* dw_b  = (const float*)d_in[13];
    const float* mln_g = (const float*)d_in[14];
    const float* mln_b = (const float*)d_in[15];
    const float* fc2_w = (const float*)d_in[16];
    const float* fc2_b = (const float*)d_in[17];
    float* out = (float*)d_out;

    static int smem_set = 0;
    if (!smem_set) {
        cudaFuncSetAttribute(hgemm_kernel<0>, cudaFuncAttributeMaxDynamicSharedMemorySize, HSMEM_BYTES);
        cudaFuncSetAttribute(hgemm_kernel<1>, cudaFuncAttributeMaxDynamicSharedMemorySize, HSMEM_BYTES);
        cudaFuncSetAttribute(hgemm_kernel<2>, cudaFuncAttributeMaxDynamicSharedMemorySize, HSMEM_BYTES);
        smem_set = 1;
    }

    // norm1 on both streams
    ln_kernel<0><<<BN / 8, 256>>>(x1, ln1_g, ln1_b);
    ln_kernel<1><<<BN / 8, 256>>>(x2, ln1_g, ln1_b);
    prep_weights<<<512, 256>>>(rep_w, dw_w, fc1_w, fc2_w);

    // linear attention
    colstats_kernel<<<BB * CSPLIT, 128>>>();
    colcombine_kernel<<<BB, 128>>>();
    ctx_kernel<<<BB * NHEADS * 32, 1024>>>();
    ctx_reduce_kernel<<<16, 1024>>>();
    attq_kernel<<<BN / 32, 128>>>();

    // reprojection GEMM -> rep, then tx (f32) + y (bf16 split)
    hgemm_kernel<0><<<dim3(2, BN / 128), 256, HSMEM_BYTES>>>(rep_b, nullptr);
    txy_kernel<<<BN / 8, 256>>>(x1, x2, aln_g, aln_b, ln2_g, ln2_b);

    // MixFFN
    hgemm_kernel<1><<<dim3(4, BN / 128), 256, HSMEM_BYTES>>>(fc1_b, nullptr);
    dwlngelu_kernel<<<BN, 128>>>(dw_b, mln_g, mln_b);
    hgemm_kernel<2><<<dim3(2, BN / 128), 256, HSMEM_BYTES>>>(fc2_b, out);
}

// round 10
// speedup vs baseline: 1.0228x; 1.0228x over previous
#include <cuda_runtime.h>
#include <cuda_bf16.h>
#include <math.h>
#include <stdint.h>

#define BB     4
#define HH_    32
#define WW_    32
#define MM_    16
#define DD     128
#define NN     16384          // H*W*M
#define BN     65536          // B*N
#define D2     256
#define D4     512
#define NHEADS 4
#define HK     32
#define EPSLN  1e-5f
#define CSPLIT 256

// ---------------- scratch (device globals; no allocation allowed) ----------
__device__ __align__(16) float g_n1[BN * DD];
__device__ __align__(16) float g_n2[BN * DD];
__device__ __align__(16) float g_pmax[BB * CSPLIT * DD];
__device__ __align__(16) float g_psum[BB * CSPLIT * DD];
__device__ __align__(16) float g_cmax[BB * DD];
__device__ __align__(16) float g_cinv[BB * DD];
__device__ __align__(16) float g_ctxp[32 * BB * NHEADS * HK * HK];
__device__ __align__(16) float g_ctx[BB * NHEADS * HK * HK];
__device__ __align__(16) float g_rep[BN * D2];
__device__ __align__(16) float g_tx[BN * D2];
__device__ __align__(16) float g_h1[(size_t)BN * D4];
__device__ __align__(16) float g_dwT[27 * D4];
// pre-split bf16 GEMM A operands
__device__ __align__(16) __nv_bfloat16 g_agghi[BN * DD],        g_agglo[BN * DD];
__device__ __align__(16) __nv_bfloat16 g_yhi[BN * D2],          g_ylo[BN * D2];
__device__ __align__(16) __nv_bfloat16 g_axhi[(size_t)BN * D4], g_axlo[(size_t)BN * D4];
// pre-split bf16 weights, [N][K] K-major
__device__ __align__(16) __nv_bfloat16 g_w0hi[D2 * DD], g_w0lo[D2 * DD];   // rep
__device__ __align__(16) __nv_bfloat16 g_w1hi[D4 * D2], g_w1lo[D4 * D2];   // fc1
__device__ __align__(16) __nv_bfloat16 g_w2hi[D2 * D4], g_w2lo[D2 * D4];   // fc2

// ---------------- helpers ---------------------------------------------------
// NOTE: not volatile — dependencies are fully expressed via register
// constraints, letting ptxas interleave independent HMMAs and LDSMs.
__device__ __forceinline__ void mma16816(float* c, const uint32_t* a, const uint32_t* b) {
    asm("mma.sync.aligned.m16n8k16.row.col.f32.bf16.bf16.f32 "
        "{%0,%1,%2,%3}, {%4,%5,%6,%7}, {%8,%9}, {%0,%1,%2,%3};"
        : "+f"(c[0]), "+f"(c[1]), "+f"(c[2]), "+f"(c[3])
        : "r"(a[0]), "r"(a[1]), "r"(a[2]), "r"(a[3]), "r"(b[0]), "r"(b[1]));
}
__device__ __forceinline__ uint32_t smem_u32(const void* p) {
    uint32_t a;
    asm("{ .reg .u64 t; cvta.to.shared.u64 t, %1; cvt.u32.u64 %0, t; }" : "=r"(a) : "l"(p));
    return a;
}
__device__ __forceinline__ void ldsm_x4(uint32_t* r, uint32_t addr) {
    asm volatile("ldmatrix.sync.aligned.m8n8.x4.shared.b16 {%0,%1,%2,%3}, [%4];"
                 : "=r"(r[0]), "=r"(r[1]), "=r"(r[2]), "=r"(r[3]) : "r"(addr));
}
__device__ __forceinline__ void split_bf16(float v, uint16_t& hb, uint16_t& lb) {
    __nv_bfloat16 h = __float2bfloat16(v);
    __nv_bfloat16 l = __float2bfloat16(v - __bfloat162float(h));
    hb = __bfloat16_as_ushort(h);
    lb = __bfloat16_as_ushort(l);
}
// split a float4 and pack into uint2 (4 bf16)
__device__ __forceinline__ void split4(float4 v, uint2& hp, uint2& lp) {
    uint16_t hh[4], ll[4];
    split_bf16(v.x, hh[0], ll[0]);
    split_bf16(v.y, hh[1], ll[1]);
    split_bf16(v.z, hh[2], ll[2]);
    split_bf16(v.w, hh[3], ll[3]);
    hp.x = (uint32_t)hh[0] | ((uint32_t)hh[1] << 16);
    hp.y = (uint32_t)hh[2] | ((uint32_t)hh[3] << 16);
    lp.x = (uint32_t)ll[0] | ((uint32_t)ll[1] << 16);
    lp.y = (uint32_t)ll[2] | ((uint32_t)ll[3] << 16);
}

// ---------------- LayerNorm: one warp per row, float4 ----------------------
template <int MODE>
__global__ void ln_kernel(const float* __restrict__ x,
                          const float* __restrict__ gg,
                          const float* __restrict__ bb) {
    int gw = (blockIdx.x * blockDim.x + threadIdx.x) >> 5;
    int lane = threadIdx.x & 31;
    if (gw >= BN) return;
    float* dst = (MODE == 0) ? g_n1 : g_n2;

    const float4* xr = reinterpret_cast<const float4*>(x) + (size_t)gw * 32;
    float4 v = xr[lane];
    float s = v.x + v.y + v.z + v.w;
    float ss = v.x * v.x + v.y * v.y + v.z * v.z + v.w * v.w;
#pragma unroll
    for (int o = 16; o > 0; o >>= 1) {
        s  += __shfl_xor_sync(0xffffffffu, s, o);
        ss += __shfl_xor_sync(0xffffffffu, ss, o);
    }
    float mean = s * (1.0f / DD);
    float rstd = rsqrtf(ss * (1.0f / DD) - mean * mean + EPSLN);

    float4 gv = reinterpret_cast<const float4*>(gg)[lane];
    float4 bv = reinterpret_cast<const float4*>(bb)[lane];
    float4 r;
    r.x = (v.x - mean) * rstd * gv.x + bv.x;
    r.y = (v.y - mean) * rstd * gv.y + bv.y;
    r.z = (v.z - mean) * rstd * gv.z + bv.z;
    r.w = (v.w - mean) * rstd * gv.w + bv.w;
    reinterpret_cast<float4*>(dst)[(size_t)gw * 32 + lane] = r;
}

// ---------------- key softmax column stats over N (partials) --------------
__global__ void colstats_kernel() {
    int b = blockIdx.x >> 8, sp = blockIdx.x & (CSPLIT - 1);
    int d = threadIdx.x;
    const float* p = g_n2 + ((size_t)b * NN + sp * (NN / CSPLIT)) * DD + d;
    float m = -1e30f, s = 0.f;
    for (int i = 0; i < NN / CSPLIT; i++) {
        float v = p[(size_t)i * DD];
        float nm = fmaxf(m, v);
        s = s * __expf(m - nm) + __expf(v - nm);
        m = nm;
    }
    g_pmax[blockIdx.x * DD + d] = m;
    g_psum[blockIdx.x * DD + d] = s;
}

__global__ void colcombine_kernel() {
    int b = blockIdx.x, d = threadIdx.x;
    float m = -1e30f, s = 0.f;
    for (int sp = 0; sp < CSPLIT; sp++) {
        float pm = g_pmax[(b * CSPLIT + sp) * DD + d];
        float ps = g_psum[(b * CSPLIT + sp) * DD + d];
        float nm = fmaxf(m, pm);
        s = s * __expf(m - nm) + ps * __expf(pm - nm);
        m = nm;
    }
    g_cmax[b * DD + d] = m;
    g_cinv[b * DD + d] = 1.0f / s;
}

// ---------------- context[b,h,k,v] = sum_n key * v   (split-N partials) ---
__global__ void ctx_kernel() {
    int sp = blockIdx.x & 31;
    int h  = (blockIdx.x >> 5) & 3;
    int b  = blockIdx.x >> 7;
    int tid = threadIdx.x;
    int v = tid & 31, k = tid >> 5;

    __shared__ float cm[HK], ci[HK];
    __shared__ float ke[16][HK], vv[16][HK];
    if (tid < HK) {
        cm[tid] = g_cmax[b * DD + h * HK + tid];
        ci[tid] = g_cinv[b * DD + h * HK + tid];
    }
    float acc = 0.f;
    int n0 = sp * 512;
    int tt = tid >> 6, col = tid & 63;
    for (int t0 = 0; t0 < 512; t0 += 16) {
        __syncthreads();
        int n = n0 + t0 + tt;
        size_t base = ((size_t)b * NN + n) * DD + h * HK;
        if (col < HK) ke[tt][col] = __expf(g_n2[base + col] - cm[col]) * ci[col];
        else          vv[tt][col - HK] = g_n1[base + col - HK];
        __syncthreads();
#pragma unroll
        for (int t = 0; t < 16; t++) acc += ke[t][k] * vv[t][v];
    }
    g_ctxp[(size_t)sp * (BB * NHEADS * HK * HK) +
           (((b * NHEADS + h) * HK + k) * HK + v)] = acc;
}

__global__ void ctx_reduce_kernel() {
    int i = blockIdx.x * 1024 + threadIdx.x;
    float s = 0.f;
    for (int sp = 0; sp < 32; sp++) s += g_ctxp[sp * (BB * NHEADS * HK * HK) + i];
    g_ctx[i] = s;
}

// ---------------- weight re-layouts + bf16 splits ---------------------------
__global__ void prep_weights(const float* __restrict__ rep_w,
                             const float* __restrict__ dw_w,
                             const float* __restrict__ fc1_w,
                             const float* __restrict__ fc2_w) {
    int i = blockIdx.x * 256 + threadIdx.x;
    uint16_t hb, lb;
    if (i < D2 * DD) {                      // rep_w already [N=256][K=128]
        split_bf16(rep_w[i], hb, lb);
        g_w0hi[i] = __ushort_as_bfloat16(hb); g_w0lo[i] = __ushort_as_bfloat16(lb);
    }
    if (i < D4 * D2) {                      // fc1_w [K=256][N=512] -> [n][k]
        int n = i >> 8, k = i & 255;
        split_bf16(fc1_w[k * D4 + n], hb, lb);
        g_w1hi[i] = __ushort_as_bfloat16(hb); g_w1lo[i] = __ushort_as_bfloat16(lb);
    }
    if (i < D2 * D4) {                      // fc2_w [K=512][N=256] -> [n][k]
        int n = i >> 9, k = i & 511;
        split_bf16(fc2_w[k * D2 + n], hb, lb);
        g_w2hi[i] = __ushort_as_bfloat16(hb); g_w2lo[i] = __ushort_as_bfloat16(lb);
    }
    if (i < 27 * D4) {                      // dw_w [c][27] -> [tap][c]
        int c = i / 27, t = i % 27;
        g_dwT[t * D4 + c] = dw_w[i];
    }
}

// ---------------- query softmax + att matvec -> agg (split bf16) ----------
__global__ void attq_kernel() {
    __shared__ float sn2[32][129];
    __shared__ float sctx[NHEADS][HK][HK];
    int b = blockIdx.x >> 9;
    int tok0 = (blockIdx.x & 511) * 32;
    int tid = threadIdx.x;

    for (int i = tid; i < NHEADS * HK * HK; i += 128)
        ((float*)sctx)[i] = g_ctx[b * (NHEADS * HK * HK) + i];
    for (int i = tid; i < 32 * 128; i += 128) {
        int r = i >> 7, c = i & 127;
        sn2[r][c] = g_n2[((size_t)b * NN + tok0 + r) * DD + c];
    }
    __syncthreads();

    int h = tid >> 5, t = tid & 31;
    float q[HK];
    float mx = -1e30f;
#pragma unroll
    for (int k = 0; k < HK; k++) { q[k] = sn2[t][h * HK + k]; mx = fmaxf(mx, q[k]); }
    float sum = 0.f;
#pragma unroll
    for (int k = 0; k < HK; k++) { q[k] = __expf(q[k] - mx); sum += q[k]; }
    float inv = 1.0f / sum;

    float av[HK];
#pragma unroll
    for (int j = 0; j < HK; j++) av[j] = 0.f;
#pragma unroll
    for (int k = 0; k < HK; k++) {
        float qk = q[k] * inv;
#pragma unroll
        for (int j = 0; j < HK; j++) av[j] += qk * sctx[h][k][j];
    }
    __syncthreads();
#pragma unroll
    for (int j = 0; j < HK; j++) sn2[t][h * HK + j] = av[j];
    __syncthreads();
    // scalar LDS reads (row stride 129 floats is not 16B-aligned)
    for (int i = tid; i < 32 * 32; i += 128) {
        int r = i >> 5, c4 = i & 31;
        float4 v;
        v.x = sn2[r][c4 * 4 + 0];
        v.y = sn2[r][c4 * 4 + 1];
        v.z = sn2[r][c4 * 4 + 2];
        v.w = sn2[r][c4 * 4 + 3];
        uint2 hp, lp;
        split4(v, hp, lp);
        size_t idx = ((size_t)b * NN + tok0 + r) * DD + c4 * 4;
        *reinterpret_cast<uint2*>(&g_agghi[idx]) = hp;
        *reinterpret_cast<uint2*>(&g_agglo[idx]) = lp;
    }
}

// ---------------- HMMA bf16 3-term split GEMM (ldmatrix fragments) ----------
// WHICH 0: agg[65536,128] @ w0[256,128]^T            -> g_rep
// WHICH 1: y  [65536,256] @ w1[512,256]^T            -> g_h1
// WHICH 2: ax [65536,512] @ w2[256,512]^T + b + tx   -> Cout (d_out)
// CTA tile 128x128, BK=32, 8 warps (4m x 2n), warp tile 32x64.
#define LDKP 40                      // padded bf16 k-stride (80B rows: LDSM conflict-free)
#define ATILE (128 * LDKP)           // elems per matrix per stage
#define HSMEM_BYTES (8 * ATILE * 2)  // 4 matrices x 2 stages = 81920 B

template <int WHICH>
__global__ void __launch_bounds__(256) hgemm_kernel(const float* __restrict__ bias,
                                                    float* __restrict__ CoutP) {
    constexpr int K  = (WHICH == 0) ? 128 : (WHICH == 1) ? 256 : 512;
    constexpr int Nc = (WHICH == 1) ? 512 : 256;
    constexpr int CHUNKS = K / 32;

    const __nv_bfloat16* Ah = (WHICH == 0) ? g_agghi : (WHICH == 1) ? g_yhi : g_axhi;
    const __nv_bfloat16* Al = (WHICH == 0) ? g_agglo : (WHICH == 1) ? g_ylo : g_axlo;
    const __nv_bfloat16* Bh = (WHICH == 0) ? g_w0hi : (WHICH == 1) ? g_w1hi : g_w2hi;
    const __nv_bfloat16* Bl = (WHICH == 0) ? g_w0lo : (WHICH == 1) ? g_w1lo : g_w2lo;
    float* C = (WHICH == 0) ? g_rep : (WHICH == 1) ? g_h1 : CoutP;

    extern __shared__ __align__(16) __nv_bfloat16 sm_bf[];
    __nv_bfloat16* sAh = sm_bf;               // [2][ATILE]
    __nv_bfloat16* sAl = sAh + 2 * ATILE;
    __nv_bfloat16* sBh = sAl + 2 * ATILE;
    __nv_bfloat16* sBl = sBh + 2 * ATILE;

    int tid = threadIdx.x, lane = tid & 31, wid = tid >> 5;
    int wm = wid >> 1, wn = wid & 1;
    int m0 = blockIdx.y * 128, n0 = blockIdx.x * 128;
    int g = lane >> 2, t4 = lane & 3;

    int ar_ = tid >> 2, aq_ = tid & 3;  // A loader: row ar_+64i, uint4-col aq_ (8 bf16)
    int bn = tid >> 2, bq = tid & 3;    // B loader: row bn+64i, uint4-col bq

    // ldmatrix per-lane element offsets (in bf16 elems, relative to stage base)
    int a_row = wm * 32 + (lane & 15);
    int a_elem = a_row * LDKP + (lane >> 4) * 8;
    int b_row = wn * 64 + (lane & 7) + ((lane >> 4) << 3);
    int b_elem = b_row * LDKP + ((lane >> 3) & 1) * 8;

    uint32_t sAh_u = smem_u32(sAh), sAl_u = smem_u32(sAl);
    uint32_t sBh_u = smem_u32(sBh), sBl_u = smem_u32(sBl);

    uint4 ahr[2], alr[2], bhr[2], blr[2];
    float acc[2][8][4] = {};

    // ---- prologue: LDG chunk 0
#pragma unroll
    for (int i = 0; i < 2; i++) {
        size_t aoff = (size_t)(m0 + ar_ + 64 * i) * K + aq_ * 8;
        ahr[i] = *reinterpret_cast<const uint4*>(Ah + aoff);
        alr[i] = *reinterpret_cast<const uint4*>(Al + aoff);
        size_t boff = (size_t)(n0 + bn + 64 * i) * K + bq * 8;
        bhr[i] = *reinterpret_cast<const uint4*>(Bh + boff);
        blr[i] = *reinterpret_cast<const uint4*>(Bl + boff);
    }
    // STS stage 0
#pragma unroll
    for (int i = 0; i < 2; i++) {
        int ra = ar_ + 64 * i, rb = bn + 64 * i;
        *reinterpret_cast<uint4*>(sAh + ra * LDKP + aq_ * 8) = ahr[i];
        *reinterpret_cast<uint4*>(sAl + ra * LDKP + aq_ * 8) = alr[i];
        *reinterpret_cast<uint4*>(sBh + rb * LDKP + bq * 8) = bhr[i];
        *reinterpret_cast<uint4*>(sBl + rb * LDKP + bq * 8) = blr[i];
    }
    __syncthreads();

    for (int c = 0; c < CHUNKS; c++) {
        int s = c & 1;
        if (c + 1 < CHUNKS) {  // prefetch next chunk
            int k0 = (c + 1) * 32;
#pragma unroll
            for (int i = 0; i < 2; i++) {
                size_t aoff = (size_t)(m0 + ar_ + 64 * i) * K + k0 + aq_ * 8;
                ahr[i] = *reinterpret_cast<const uint4*>(Ah + aoff);
                alr[i] = *reinterpret_cast<const uint4*>(Al + aoff);
                size_t boff = (size_t)(n0 + bn + 64 * i) * K + k0 + bq * 8;
                bhr[i] = *reinterpret_cast<const uint4*>(Bh + boff);
                blr[i] = *reinterpret_cast<const uint4*>(Bl + boff);
            }
        }
        uint32_t stg = (uint32_t)(s * ATILE * 2);  // stage byte offset

#pragma unroll
        for (int kk = 0; kk < 32; kk += 16) {
            uint32_t ah[2][4], al[2][4], bh[8][2], bl[8][2];
            uint32_t a_base = stg + (uint32_t)(a_elem + kk) * 2;
            uint32_t b_base = stg + (uint32_t)(b_elem + kk) * 2;
#pragma unroll
            for (int mt = 0; mt < 2; mt++) {
                uint32_t off = a_base + (uint32_t)(mt * 16 * LDKP) * 2;
                ldsm_x4(ah[mt], sAh_u + off);
                ldsm_x4(al[mt], sAl_u + off);
            }
#pragma unroll
            for (int p = 0; p < 4; p++) {
                uint32_t off = b_base + (uint32_t)(p * 16 * LDKP) * 2;
                uint32_t th[4], tl[4];
                ldsm_x4(th, sBh_u + off);
                ldsm_x4(tl, sBl_u + off);
                bh[2 * p][0] = th[0]; bh[2 * p][1] = th[1];
                bh[2 * p + 1][0] = th[2]; bh[2 * p + 1][1] = th[3];
                bl[2 * p][0] = tl[0]; bl[2 * p][1] = tl[1];
                bl[2 * p + 1][0] = tl[2]; bl[2 * p + 1][1] = tl[3];
            }
            // term-major order: consecutive MMAs hit 16 DISTINCT accumulators,
            // so same-acc reuse is 16 issues apart (covers HMMA latency).
#pragma unroll
            for (int mt = 0; mt < 2; mt++)
#pragma unroll
                for (int nt = 0; nt < 8; nt++)
                    mma16816(acc[mt][nt], ah[mt], bh[nt]);
#pragma unroll
            for (int mt = 0; mt < 2; mt++)
#pragma unroll
                for (int nt = 0; nt < 8; nt++)
                    mma16816(acc[mt][nt], al[mt], bh[nt]);
#pragma unroll
            for (int mt = 0; mt < 2; mt++)
#pragma unroll
                for (int nt = 0; nt < 8; nt++)
                    mma16816(acc[mt][nt], ah[mt], bl[nt]);
        }

        if (c + 1 < CHUNKS) {  // STS next stage
            int s1 = (c + 1) & 1;
#pragma unroll
            for (int i = 0; i < 2; i++) {
                int ra = ar_ + 64 * i, rb = bn + 64 * i;
                *reinterpret_cast<uint4*>(sAh + s1 * ATILE + ra * LDKP + aq_ * 8) = ahr[i];
                *reinterpret_cast<uint4*>(sAl + s1 * ATILE + ra * LDKP + aq_ * 8) = alr[i];
                *reinterpret_cast<uint4*>(sBh + s1 * ATILE + rb * LDKP + bq * 8) = bhr[i];
                *reinterpret_cast<uint4*>(sBl + s1 * ATILE + rb * LDKP + bq * 8) = blr[i];
            }
        }
        __syncthreads();
    }

    // ---- epilogue
#pragma unroll
    for (int mt = 0; mt < 2; mt++) {
        int r0 = m0 + wm * 32 + mt * 16 + g;
#pragma unroll
        for (int nt = 0; nt < 8; nt++) {
            int ccol = n0 + wn * 64 + nt * 8 + t4 * 2;
            float2 bv = *reinterpret_cast<const float2*>(bias + ccol);
            float2 o0, o1;
            o0.x = acc[mt][nt][0] + bv.x; o0.y = acc[mt][nt][1] + bv.y;
            o1.x = acc[mt][nt][2] + bv.x; o1.y = acc[mt][nt][3] + bv.y;
            if (WHICH == 2) {
                float2 t0 = *reinterpret_cast<const float2*>(&g_tx[(size_t)r0 * Nc + ccol]);
                float2 t1 = *reinterpret_cast<const float2*>(&g_tx[(size_t)(r0 + 8) * Nc + ccol]);
                o0.x += t0.x; o0.y += t0.y; o1.x += t1.x; o1.y += t1.y;
            }
            *reinterpret_cast<float2*>(&C[(size_t)r0 * Nc + ccol]) = o0;
            *reinterpret_cast<float2*>(&C[(size_t)(r0 + 8) * Nc + ccol]) = o1;
        }
    }
}

// ---- tx = LN(rep)+concat(x1,x2) (f32)  AND  y = LN(tx) split bf16 ----------
__global__ void txy_kernel(const float* __restrict__ x1, const float* __restrict__ x2,
                           const float* __restrict__ ag, const float* __restrict__ ab,
                           const float* __restrict__ g2, const float* __restrict__ b2) {
    int gw = (blockIdx.x * blockDim.x + threadIdx.x) >> 5;
    int lane = threadIdx.x & 31;
    if (gw >= BN) return;
    const float4* rr = reinterpret_cast<const float4*>(g_rep) + (size_t)gw * 64;
    float4 v[2];
    float s = 0.f, ss = 0.f;
#pragma unroll
    for (int i = 0; i < 2; i++) {
        v[i] = rr[i * 32 + lane];
        s  += v[i].x + v[i].y + v[i].z + v[i].w;
        ss += v[i].x * v[i].x + v[i].y * v[i].y + v[i].z * v[i].z + v[i].w * v[i].w;
    }
#pragma unroll
    for (int o = 16; o > 0; o >>= 1) {
        s  += __shfl_xor_sync(0xffffffffu, s, o);
        ss += __shfl_xor_sync(0xffffffffu, ss, o);
    }
    float mean = s * (1.0f / D2);
    float rstd = rsqrtf(ss * (1.0f / D2) - mean * mean + EPSLN);

    const float4* g4 = reinterpret_cast<const float4*>(ag);
    const float4* b4 = reinterpret_cast<const float4*>(ab);
    const float4* x14 = reinterpret_cast<const float4*>(x1) + (size_t)gw * 32;
    const float4* x24 = reinterpret_cast<const float4*>(x2) + (size_t)gw * 32;
    float4* txr = reinterpret_cast<float4*>(g_tx) + (size_t)gw * 64;

    float4 tv[2];
    float s2 = 0.f, ss2 = 0.f;
#pragma unroll
    for (int i = 0; i < 2; i++) {
        int c4 = i * 32 + lane;
        float4 gv = g4[c4], bv = b4[c4];
        float4 cat = (i == 0) ? x14[lane] : x24[lane];
        float4 r;
        r.x = (v[i].x - mean) * rstd * gv.x + bv.x + cat.x;
        r.y = (v[i].y - mean) * rstd * gv.y + bv.y + cat.y;
        r.z = (v[i].z - mean) * rstd * gv.z + bv.z + cat.z;
        r.w = (v[i].w - mean) * rstd * gv.w + bv.w + cat.w;
        txr[c4] = r;
        tv[i] = r;
        s2  += r.x + r.y + r.z + r.w;
        ss2 += r.x * r.x + r.y * r.y + r.z * r.z + r.w * r.w;
    }
#pragma unroll
    for (int o = 16; o > 0; o >>= 1) {
        s2  += __shfl_xor_sync(0xffffffffu, s2, o);
        ss2 += __shfl_xor_sync(0xffffffffu, ss2, o);
    }
    float mean2 = s2 * (1.0f / D2);
    float rstd2 = rsqrtf(ss2 * (1.0f / D2) - mean2 * mean2 + EPSLN);

    const float4* g24 = reinterpret_cast<const float4*>(g2);
    const float4* b24 = reinterpret_cast<const float4*>(b2);
#pragma unroll
    for (int i = 0; i < 2; i++) {
        int c4 = i * 32 + lane;
        float4 gv = g24[c4], bv = b24[c4], r;
        r.x = (tv[i].x - mean2) * rstd2 * gv.x + bv.x;
        r.y = (tv[i].y - mean2) * rstd2 * gv.y + bv.y;
        r.z = (tv[i].z - mean2) * rstd2 * gv.z + bv.z;
        r.w = (tv[i].w - mean2) * rstd2 * gv.w + bv.w;
        uint2 hp, lp;
        split4(r, hp, lp);
        size_t idx = (size_t)gw * D2 + c4 * 4;
        *reinterpret_cast<uint2*>(&g_yhi[idx]) = hp;
        *reinterpret_cast<uint2*>(&g_ylo[idx]) = lp;
    }
}

// ---- dwconv + bias + h1, then LN + GELU, write ax split bf16 ---------------
__global__ void dwlngelu_kernel(const float* __restrict__ dwb,
                                const float* __restrict__ mg,
                                const float* __restrict__ mb) {
    __shared__ float red[8];
    int n = blockIdx.x;
    int loc = n & (NN - 1);
    int m_ = loc & 15, w_ = (loc >> 4) & 31, h_ = loc >> 9;
    int tc = threadIdx.x;
    int lane = tc & 31, wrp = tc >> 5;
    const float4* x4 = reinterpret_cast<const float4*>(g_h1);

    float4 acc = x4[(size_t)n * 128 + tc];
    float4 bv = reinterpret_cast<const float4*>(dwb)[tc];
    acc.x += bv.x; acc.y += bv.y; acc.z += bv.z; acc.w += bv.w;

#pragma unroll
    for (int di = -1; di <= 1; di++) {
        int hh = h_ + di;
        if (hh < 0 || hh >= HH_) continue;
#pragma unroll
        for (int dj = -1; dj <= 1; dj++) {
            int ww = w_ + dj;
            if (ww < 0 || ww >= WW_) continue;
#pragma unroll
            for (int dk = -1; dk <= 1; dk++) {
                int mm = m_ + dk;
                if (mm < 0 || mm >= MM_) continue;
                int nn = n + di * (WW_ * MM_) + dj * MM_ + dk;
                float4 xv = x4[(size_t)nn * 128 + tc];
                float4 wt = reinterpret_cast<const float4*>(
                    g_dwT)[((di + 1) * 9 + (dj + 1) * 3 + (dk + 1)) * 128 + tc];
                acc.x += xv.x * wt.x; acc.y += xv.y * wt.y;
                acc.z += xv.z * wt.z; acc.w += xv.w * wt.w;
            }
        }
    }

    // block LN over 512 channels
    float s = acc.x + acc.y + acc.z + acc.w;
    float ss = acc.x * acc.x + acc.y * acc.y + acc.z * acc.z + acc.w * acc.w;
#pragma unroll
    for (int o = 16; o > 0; o >>= 1) {
        s  += __shfl_xor_sync(0xffffffffu, s, o);
        ss += __shfl_xor_sync(0xffffffffu, ss, o);
    }
    if (lane == 0) { red[wrp] = s; red[4 + wrp] = ss; }
    __syncthreads();
    s = red[0] + red[1] + red[2] + red[3];
    ss = red[4] + red[5] + red[6] + red[7];
    float mean = s * (1.0f / D4);
    float rstd = rsqrtf(ss * (1.0f / D4) - mean * mean + EPSLN);

    float4 gv = reinterpret_cast<const float4*>(mg)[tc];
    float4 b2 = reinterpret_cast<const float4*>(mb)[tc];
    float4 r;
    float t;
    t = (acc.x - mean) * rstd * gv.x + b2.x; r.x = t * normcdff(t);
    t = (acc.y - mean) * rstd * gv.y + b2.y; r.y = t * normcdff(t);
    t = (acc.z - mean) * rstd * gv.z + b2.z; r.z = t * normcdff(t);
    t = (acc.w - mean) * rstd * gv.w + b2.w; r.w = t * normcdff(t);

    uint2 hp, lp;
    split4(r, hp, lp);
    size_t idx = (size_t)n * D4 + tc * 4;
    *reinterpret_cast<uint2*>(&g_axhi[idx]) = hp;
    *reinterpret_cast<uint2*>(&g_axlo[idx]) = lp;
}

// ---------------------------------------------------------------------------
extern "C" void kernel_launch(void* const* d_in, const int* in_sizes, int n_in,
                              void* d_out, int out_size) {
    const float* x1    = (const float*)d_in[0];
    const float* x2    = (const float*)d_in[1];
    const float* ln1_g = (const float*)d_in[2];
    const float* ln1_b = (const float*)d_in[3];
    const float* rep_w = (const float*)d_in[4];
    const float* rep_b = (const float*)d_in[5];
    const float* aln_g = (const float*)d_in[6];
    const float* aln_b = (const float*)d_in[7];
    const float* ln2_g = (const float*)d_in[8];
    const float* ln2_b = (const float*)d_in[9];
    const float* fc1_w = (const float*)d_in[10];
    const float* fc1_b = (const float*)d_in[11];
    const float* dw_w  = (const float*)d_in[12];
    const float* dw_b  = (const float*)d_in[13];
    const float* mln_g = (const float*)d_in[14];
    const float* mln_b = (const float*)d_in[15];
    const float* fc2_w = (const float*)d_in[16];
    const float* fc2_b = (const float*)d_in[17];
    float* out = (float*)d_out;

    static int smem_set = 0;
    if (!smem_set) {
        cudaFuncSetAttribute(hgemm_kernel<0>, cudaFuncAttributeMaxDynamicSharedMemorySize, HSMEM_BYTES);
        cudaFuncSetAttribute(hgemm_kernel<1>, cudaFuncAttributeMaxDynamicSharedMemorySize, HSMEM_BYTES);
        cudaFuncSetAttribute(hgemm_kernel<2>, cudaFuncAttributeMaxDynamicSharedMemorySize, HSMEM_BYTES);
        smem_set = 1;
    }

    // norm1 on both streams
    ln_kernel<0><<<BN / 8, 256>>>(x1, ln1_g, ln1_b);
    ln_kernel<1><<<BN / 8, 256>>>(x2, ln1_g, ln1_b);
    prep_weights<<<512, 256>>>(rep_w, dw_w, fc1_w, fc2_w);

    // linear attention
    colstats_kernel<<<BB * CSPLIT, 128>>>();
    colcombine_kernel<<<BB, 128>>>();
    ctx_kernel<<<BB * NHEADS * 32, 1024>>>();
    ctx_reduce_kernel<<<16, 1024>>>();
    attq_kernel<<<BN / 32, 128>>>();

    // reprojection GEMM -> rep, then tx (f32) + y (bf16 split)
    hgemm_kernel<0><<<dim3(2, BN / 128), 256, HSMEM_BYTES>>>(rep_b, nullptr);
    txy_kernel<<<BN / 8, 256>>>(x1, x2, aln_g, aln_b, ln2_g, ln2_b);

    // MixFFN
    hgemm_kernel<1><<<dim3(4, BN / 128), 256, HSMEM_BYTES>>>(fc1_b, nullptr);
    dwlngelu_kernel<<<BN, 128>>>(dw_b, mln_g, mln_b);
    hgemm_kernel<2><<<dim3(2, BN / 128), 256, HSMEM_BYTES>>>(fc2_b, out);
}

// round 11
// speedup vs baseline: 1.0230x; 1.0002x over previous
#include <cuda_runtime.h>
#include <cuda_bf16.h>
#include <math.h>
#include <stdint.h>

#define BB     4
#define HH_    32
#define WW_    32
#define MM_    16
#define DD     128
#define NN     16384          // H*W*M
#define BN     65536          // B*N
#define D2     256
#define D4     512
#define NHEADS 4
#define HK     32
#define EPSLN  1e-5f
#define CSPLIT 256

// ---------------- scratch (device globals; no allocation allowed) ----------
__device__ __align__(16) float g_n1[BN * DD];
__device__ __align__(16) float g_n2[BN * DD];
__device__ __align__(16) float g_pmax[BB * CSPLIT * DD];
__device__ __align__(16) float g_psum[BB * CSPLIT * DD];
__device__ __align__(16) float g_cmax[BB * DD];
__device__ __align__(16) float g_cinv[BB * DD];
__device__ __align__(16) float g_ctxp[32 * BB * NHEADS * HK * HK];
__device__ __align__(16) float g_ctx[BB * NHEADS * HK * HK];
__device__ __align__(16) float g_rep[BN * D2];
__device__ __align__(16) float g_tx[BN * D2];
__device__ __align__(16) float g_h1[(size_t)BN * D4];
__device__ __align__(16) float g_dwT[27 * D4];
// pre-split bf16 GEMM A operands
__device__ __align__(16) __nv_bfloat16 g_agghi[BN * DD],        g_agglo[BN * DD];
__device__ __align__(16) __nv_bfloat16 g_yhi[BN * D2],          g_ylo[BN * D2];
__device__ __align__(16) __nv_bfloat16 g_axhi[(size_t)BN * D4], g_axlo[(size_t)BN * D4];
// pre-split bf16 weights, [N][K] K-major
__device__ __align__(16) __nv_bfloat16 g_w0hi[D2 * DD], g_w0lo[D2 * DD];   // rep
__device__ __align__(16) __nv_bfloat16 g_w1hi[D4 * D2], g_w1lo[D4 * D2];   // fc1
__device__ __align__(16) __nv_bfloat16 g_w2hi[D2 * D4], g_w2lo[D2 * D4];   // fc2

// ---------------- helpers ---------------------------------------------------
// NOTE: not volatile — dependencies are fully expressed via register
// constraints, letting ptxas interleave independent HMMAs and LDSMs.
__device__ __forceinline__ void mma16816(float* c, const uint32_t* a, const uint32_t* b) {
    asm("mma.sync.aligned.m16n8k16.row.col.f32.bf16.bf16.f32 "
        "{%0,%1,%2,%3}, {%4,%5,%6,%7}, {%8,%9}, {%0,%1,%2,%3};"
        : "+f"(c[0]), "+f"(c[1]), "+f"(c[2]), "+f"(c[3])
        : "r"(a[0]), "r"(a[1]), "r"(a[2]), "r"(a[3]), "r"(b[0]), "r"(b[1]));
}
__device__ __forceinline__ uint32_t smem_u32(const void* p) {
    uint32_t a;
    asm("{ .reg .u64 t; cvta.to.shared.u64 t, %1; cvt.u32.u64 %0, t; }" : "=r"(a) : "l"(p));
    return a;
}
__device__ __forceinline__ void ldsm_x4(uint32_t* r, uint32_t addr) {
    asm volatile("ldmatrix.sync.aligned.m8n8.x4.shared.b16 {%0,%1,%2,%3}, [%4];"
                 : "=r"(r[0]), "=r"(r[1]), "=r"(r[2]), "=r"(r[3]) : "r"(addr));
}
__device__ __forceinline__ void split_bf16(float v, uint16_t& hb, uint16_t& lb) {
    __nv_bfloat16 h = __float2bfloat16(v);
    __nv_bfloat16 l = __float2bfloat16(v - __bfloat162float(h));
    hb = __bfloat16_as_ushort(h);
    lb = __bfloat16_as_ushort(l);
}
// split a float4 and pack into uint2 (4 bf16)
__device__ __forceinline__ void split4(float4 v, uint2& hp, uint2& lp) {
    uint16_t hh[4], ll[4];
    split_bf16(v.x, hh[0], ll[0]);
    split_bf16(v.y, hh[1], ll[1]);
    split_bf16(v.z, hh[2], ll[2]);
    split_bf16(v.w, hh[3], ll[3]);
    hp.x = (uint32_t)hh[0] | ((uint32_t)hh[1] << 16);
    hp.y = (uint32_t)hh[2] | ((uint32_t)hh[3] << 16);
    lp.x = (uint32_t)ll[0] | ((uint32_t)ll[1] << 16);
    lp.y = (uint32_t)ll[2] | ((uint32_t)ll[3] << 16);
}

// ---------------- LayerNorm: one warp per row, float4 ----------------------
template <int MODE>
__global__ void ln_kernel(const float* __restrict__ x,
                          const float* __restrict__ gg,
                          const float* __restrict__ bb) {
    int gw = (blockIdx.x * blockDim.x + threadIdx.x) >> 5;
    int lane = threadIdx.x & 31;
    if (gw >= BN) return;
    float* dst = (MODE == 0) ? g_n1 : g_n2;

    const float4* xr = reinterpret_cast<const float4*>(x) + (size_t)gw * 32;
    float4 v = xr[lane];
    float s = v.x + v.y + v.z + v.w;
    float ss = v.x * v.x + v.y * v.y + v.z * v.z + v.w * v.w;
#pragma unroll
    for (int o = 16; o > 0; o >>= 1) {
        s  += __shfl_xor_sync(0xffffffffu, s, o);
        ss += __shfl_xor_sync(0xffffffffu, ss, o);
    }
    float mean = s * (1.0f / DD);
    float rstd = rsqrtf(ss * (1.0f / DD) - mean * mean + EPSLN);

    float4 gv = reinterpret_cast<const float4*>(gg)[lane];
    float4 bv = reinterpret_cast<const float4*>(bb)[lane];
    float4 r;
    r.x = (v.x - mean) * rstd * gv.x + bv.x;
    r.y = (v.y - mean) * rstd * gv.y + bv.y;
    r.z = (v.z - mean) * rstd * gv.z + bv.z;
    r.w = (v.w - mean) * rstd * gv.w + bv.w;
    reinterpret_cast<float4*>(dst)[(size_t)gw * 32 + lane] = r;
}

// ---------------- key softmax column stats over N (partials) --------------
__global__ void colstats_kernel() {
    int b = blockIdx.x >> 8, sp = blockIdx.x & (CSPLIT - 1);
    int d = threadIdx.x;
    const float* p = g_n2 + ((size_t)b * NN + sp * (NN / CSPLIT)) * DD + d;
    float m = -1e30f, s = 0.f;
    for (int i = 0; i < NN / CSPLIT; i++) {
        float v = p[(size_t)i * DD];
        float nm = fmaxf(m, v);
        s = s * __expf(m - nm) + __expf(v - nm);
        m = nm;
    }
    g_pmax[blockIdx.x * DD + d] = m;
    g_psum[blockIdx.x * DD + d] = s;
}

__global__ void colcombine_kernel() {
    int b = blockIdx.x, d = threadIdx.x;
    float m = -1e30f, s = 0.f;
    for (int sp = 0; sp < CSPLIT; sp++) {
        float pm = g_pmax[(b * CSPLIT + sp) * DD + d];
        float ps = g_psum[(b * CSPLIT + sp) * DD + d];
        float nm = fmaxf(m, pm);
        s = s * __expf(m - nm) + ps * __expf(pm - nm);
        m = nm;
    }
    g_cmax[b * DD + d] = m;
    g_cinv[b * DD + d] = 1.0f / s;
}

// ---------------- context[b,h,k,v] = sum_n key * v   (split-N partials) ---
__global__ void ctx_kernel() {
    int sp = blockIdx.x & 31;
    int h  = (blockIdx.x >> 5) & 3;
    int b  = blockIdx.x >> 7;
    int tid = threadIdx.x;
    int v = tid & 31, k = tid >> 5;

    __shared__ float cm[HK], ci[HK];
    __shared__ float ke[16][HK], vv[16][HK];
    if (tid < HK) {
        cm[tid] = g_cmax[b * DD + h * HK + tid];
        ci[tid] = g_cinv[b * DD + h * HK + tid];
    }
    float acc = 0.f;
    int n0 = sp * 512;
    int tt = tid >> 6, col = tid & 63;
    for (int t0 = 0; t0 < 512; t0 += 16) {
        __syncthreads();
        int n = n0 + t0 + tt;
        size_t base = ((size_t)b * NN + n) * DD + h * HK;
        if (col < HK) ke[tt][col] = __expf(g_n2[base + col] - cm[col]) * ci[col];
        else          vv[tt][col - HK] = g_n1[base + col - HK];
        __syncthreads();
#pragma unroll
        for (int t = 0; t < 16; t++) acc += ke[t][k] * vv[t][v];
    }
    g_ctxp[(size_t)sp * (BB * NHEADS * HK * HK) +
           (((b * NHEADS + h) * HK + k) * HK + v)] = acc;
}

__global__ void ctx_reduce_kernel() {
    int i = blockIdx.x * 1024 + threadIdx.x;
    float s = 0.f;
    for (int sp = 0; sp < 32; sp++) s += g_ctxp[sp * (BB * NHEADS * HK * HK) + i];
    g_ctx[i] = s;
}

// ---------------- weight re-layouts + bf16 splits ---------------------------
__global__ void prep_weights(const float* __restrict__ rep_w,
                             const float* __restrict__ dw_w,
                             const float* __restrict__ fc1_w,
                             const float* __restrict__ fc2_w) {
    int i = blockIdx.x * 256 + threadIdx.x;
    uint16_t hb, lb;
    if (i < D2 * DD) {                      // rep_w already [N=256][K=128]
        split_bf16(rep_w[i], hb, lb);
        g_w0hi[i] = __ushort_as_bfloat16(hb); g_w0lo[i] = __ushort_as_bfloat16(lb);
    }
    if (i < D4 * D2) {                      // fc1_w [K=256][N=512] -> [n][k]
        int n = i >> 8, k = i & 255;
        split_bf16(fc1_w[k * D4 + n], hb, lb);
        g_w1hi[i] = __ushort_as_bfloat16(hb); g_w1lo[i] = __ushort_as_bfloat16(lb);
    }
    if (i < D2 * D4) {                      // fc2_w [K=512][N=256] -> [n][k]
        int n = i >> 9, k = i & 511;
        split_bf16(fc2_w[k * D2 + n], hb, lb);
        g_w2hi[i] = __ushort_as_bfloat16(hb); g_w2lo[i] = __ushort_as_bfloat16(lb);
    }
    if (i < 27 * D4) {                      // dw_w [c][27] -> [tap][c]
        int c = i / 27, t = i % 27;
        g_dwT[t * D4 + c] = dw_w[i];
    }
}

// ---------------- query softmax + att matvec -> agg (split bf16) ----------
__global__ void attq_kernel() {
    __shared__ float sn2[32][129];
    __shared__ float sctx[NHEADS][HK][HK];
    int b = blockIdx.x >> 9;
    int tok0 = (blockIdx.x & 511) * 32;
    int tid = threadIdx.x;

    for (int i = tid; i < NHEADS * HK * HK; i += 128)
        ((float*)sctx)[i] = g_ctx[b * (NHEADS * HK * HK) + i];
    for (int i = tid; i < 32 * 128; i += 128) {
        int r = i >> 7, c = i & 127;
        sn2[r][c] = g_n2[((size_t)b * NN + tok0 + r) * DD + c];
    }
    __syncthreads();

    int h = tid >> 5, t = tid & 31;
    float q[HK];
    float mx = -1e30f;
#pragma unroll
    for (int k = 0; k < HK; k++) { q[k] = sn2[t][h * HK + k]; mx = fmaxf(mx, q[k]); }
    float sum = 0.f;
#pragma unroll
    for (int k = 0; k < HK; k++) { q[k] = __expf(q[k] - mx); sum += q[k]; }
    float inv = 1.0f / sum;

    float av[HK];
#pragma unroll
    for (int j = 0; j < HK; j++) av[j] = 0.f;
#pragma unroll
    for (int k = 0; k < HK; k++) {
        float qk = q[k] * inv;
#pragma unroll
        for (int j = 0; j < HK; j++) av[j] += qk * sctx[h][k][j];
    }
    __syncthreads();
#pragma unroll
    for (int j = 0; j < HK; j++) sn2[t][h * HK + j] = av[j];
    __syncthreads();
    // scalar LDS reads (row stride 129 floats is not 16B-aligned)
    for (int i = tid; i < 32 * 32; i += 128) {
        int r = i >> 5, c4 = i & 31;
        float4 v;
        v.x = sn2[r][c4 * 4 + 0];
        v.y = sn2[r][c4 * 4 + 1];
        v.z = sn2[r][c4 * 4 + 2];
        v.w = sn2[r][c4 * 4 + 3];
        uint2 hp, lp;
        split4(v, hp, lp);
        size_t idx = ((size_t)b * NN + tok0 + r) * DD + c4 * 4;
        *reinterpret_cast<uint2*>(&g_agghi[idx]) = hp;
        *reinterpret_cast<uint2*>(&g_agglo[idx]) = lp;
    }
}

// ---------------- HMMA bf16 3-term split GEMM (ldmatrix fragments) ----------
// WHICH 0: agg[65536,128] @ w0[256,128]^T            -> g_rep
// WHICH 1: y  [65536,256] @ w1[512,256]^T            -> g_h1
// WHICH 2: ax [65536,512] @ w2[256,512]^T + b + tx   -> Cout (d_out)
// CTA tile 128x128, BK=32, 8 warps (4m x 2n), warp tile 32x64.
#define LDKP 40                      // padded bf16 k-stride (80B rows: LDSM conflict-free)
#define ATILE (128 * LDKP)           // elems per matrix per stage
#define HSMEM_BYTES (8 * ATILE * 2)  // 4 matrices x 2 stages = 81920 B

template <int WHICH>
__global__ void __launch_bounds__(256) hgemm_kernel(const float* __restrict__ bias,
                                                    float* __restrict__ CoutP) {
    constexpr int K  = (WHICH == 0) ? 128 : (WHICH == 1) ? 256 : 512;
    constexpr int Nc = (WHICH == 1) ? 512 : 256;
    constexpr int CHUNKS = K / 32;

    const __nv_bfloat16* Ah = (WHICH == 0) ? g_agghi : (WHICH == 1) ? g_yhi : g_axhi;
    const __nv_bfloat16* Al = (WHICH == 0) ? g_agglo : (WHICH == 1) ? g_ylo : g_axlo;
    const __nv_bfloat16* Bh = (WHICH == 0) ? g_w0hi : (WHICH == 1) ? g_w1hi : g_w2hi;
    const __nv_bfloat16* Bl = (WHICH == 0) ? g_w0lo : (WHICH == 1) ? g_w1lo : g_w2lo;
    float* C = (WHICH == 0) ? g_rep : (WHICH == 1) ? g_h1 : CoutP;

    extern __shared__ __align__(16) __nv_bfloat16 sm_bf[];
    __nv_bfloat16* sAh = sm_bf;               // [2][ATILE]
    __nv_bfloat16* sAl = sAh + 2 * ATILE;
    __nv_bfloat16* sBh = sAl + 2 * ATILE;
    __nv_bfloat16* sBl = sBh + 2 * ATILE;

    int tid = threadIdx.x, lane = tid & 31, wid = tid >> 5;
    int wm = wid >> 1, wn = wid & 1;
    int m0 = blockIdx.y * 128, n0 = blockIdx.x * 128;
    int g = lane >> 2, t4 = lane & 3;

    int ar_ = tid >> 2, aq_ = tid & 3;  // A loader: row ar_+64i, uint4-col aq_ (8 bf16)
    int bn = tid >> 2, bq = tid & 3;    // B loader: row bn+64i, uint4-col bq

    // ldmatrix per-lane element offsets (in bf16 elems, relative to stage base)
    int a_row = wm * 32 + (lane & 15);
    int a_elem = a_row * LDKP + (lane >> 4) * 8;
    int b_row = wn * 64 + (lane & 7) + ((lane >> 4) << 3);
    int b_elem = b_row * LDKP + ((lane >> 3) & 1) * 8;

    uint32_t sAh_u = smem_u32(sAh), sAl_u = smem_u32(sAl);
    uint32_t sBh_u = smem_u32(sBh), sBl_u = smem_u32(sBl);

    uint4 ahr[2], alr[2], bhr[2], blr[2];
    float acc[2][8][4] = {};

    // ---- prologue: LDG chunk 0
#pragma unroll
    for (int i = 0; i < 2; i++) {
        size_t aoff = (size_t)(m0 + ar_ + 64 * i) * K + aq_ * 8;
        ahr[i] = *reinterpret_cast<const uint4*>(Ah + aoff);
        alr[i] = *reinterpret_cast<const uint4*>(Al + aoff);
        size_t boff = (size_t)(n0 + bn + 64 * i) * K + bq * 8;
        bhr[i] = *reinterpret_cast<const uint4*>(Bh + boff);
        blr[i] = *reinterpret_cast<const uint4*>(Bl + boff);
    }
    // STS stage 0
#pragma unroll
    for (int i = 0; i < 2; i++) {
        int ra = ar_ + 64 * i, rb = bn + 64 * i;
        *reinterpret_cast<uint4*>(sAh + ra * LDKP + aq_ * 8) = ahr[i];
        *reinterpret_cast<uint4*>(sAl + ra * LDKP + aq_ * 8) = alr[i];
        *reinterpret_cast<uint4*>(sBh + rb * LDKP + bq * 8) = bhr[i];
        *reinterpret_cast<uint4*>(sBl + rb * LDKP + bq * 8) = blr[i];
    }
    __syncthreads();

    for (int c = 0; c < CHUNKS; c++) {
        int s = c & 1;
        if (c + 1 < CHUNKS) {  // prefetch next chunk
            int k0 = (c + 1) * 32;
#pragma unroll
            for (int i = 0; i < 2; i++) {
                size_t aoff = (size_t)(m0 + ar_ + 64 * i) * K + k0 + aq_ * 8;
                ahr[i] = *reinterpret_cast<const uint4*>(Ah + aoff);
                alr[i] = *reinterpret_cast<const uint4*>(Al + aoff);
                size_t boff = (size_t)(n0 + bn + 64 * i) * K + k0 + bq * 8;
                bhr[i] = *reinterpret_cast<const uint4*>(Bh + boff);
                blr[i] = *reinterpret_cast<const uint4*>(Bl + boff);
            }
        }
        uint32_t stg = (uint32_t)(s * ATILE * 2);  // stage byte offset

#pragma unroll
        for (int kk = 0; kk < 32; kk += 16) {
            uint32_t ah[2][4], al[2][4], bh[8][2], bl[8][2];
            uint32_t a_base = stg + (uint32_t)(a_elem + kk) * 2;
            uint32_t b_base = stg + (uint32_t)(b_elem + kk) * 2;
#pragma unroll
            for (int mt = 0; mt < 2; mt++) {
                uint32_t off = a_base + (uint32_t)(mt * 16 * LDKP) * 2;
                ldsm_x4(ah[mt], sAh_u + off);
                ldsm_x4(al[mt], sAl_u + off);
            }
#pragma unroll
            for (int p = 0; p < 4; p++) {
                uint32_t off = b_base + (uint32_t)(p * 16 * LDKP) * 2;
                uint32_t th[4], tl[4];
                ldsm_x4(th, sBh_u + off);
                ldsm_x4(tl, sBl_u + off);
                bh[2 * p][0] = th[0]; bh[2 * p][1] = th[1];
                bh[2 * p + 1][0] = th[2]; bh[2 * p + 1][1] = th[3];
                bl[2 * p][0] = tl[0]; bl[2 * p][1] = tl[1];
                bl[2 * p + 1][0] = tl[2]; bl[2 * p + 1][1] = tl[3];
            }
            // term-major order: consecutive MMAs hit 16 DISTINCT accumulators,
            // so same-acc reuse is 16 issues apart (covers HMMA latency).
#pragma unroll
            for (int mt = 0; mt < 2; mt++)
#pragma unroll
                for (int nt = 0; nt < 8; nt++)
                    mma16816(acc[mt][nt], ah[mt], bh[nt]);
#pragma unroll
            for (int mt = 0; mt < 2; mt++)
#pragma unroll
                for (int nt = 0; nt < 8; nt++)
                    mma16816(acc[mt][nt], al[mt], bh[nt]);
#pragma unroll
            for (int mt = 0; mt < 2; mt++)
#pragma unroll
                for (int nt = 0; nt < 8; nt++)
                    mma16816(acc[mt][nt], ah[mt], bl[nt]);
        }

        if (c + 1 < CHUNKS) {  // STS next stage
            int s1 = (c + 1) & 1;
#pragma unroll
            for (int i = 0; i < 2; i++) {
                int ra = ar_ + 64 * i, rb = bn + 64 * i;
                *reinterpret_cast<uint4*>(sAh + s1 * ATILE + ra * LDKP + aq_ * 8) = ahr[i];
                *reinterpret_cast<uint4*>(sAl + s1 * ATILE + ra * LDKP + aq_ * 8) = alr[i];
                *reinterpret_cast<uint4*>(sBh + s1 * ATILE + rb * LDKP + bq * 8) = bhr[i];
                *reinterpret_cast<uint4*>(sBl + s1 * ATILE + rb * LDKP + bq * 8) = blr[i];
            }
        }
        __syncthreads();
    }

    // ---- epilogue
#pragma unroll
    for (int mt = 0; mt < 2; mt++) {
        int r0 = m0 + wm * 32 + mt * 16 + g;
#pragma unroll
        for (int nt = 0; nt < 8; nt++) {
            int ccol = n0 + wn * 64 + nt * 8 + t4 * 2;
            float2 bv = *reinterpret_cast<const float2*>(bias + ccol);
            float2 o0, o1;
            o0.x = acc[mt][nt][0] + bv.x; o0.y = acc[mt][nt][1] + bv.y;
            o1.x = acc[mt][nt][2] + bv.x; o1.y = acc[mt][nt][3] + bv.y;
            if (WHICH == 2) {
                float2 t0 = *reinterpret_cast<const float2*>(&g_tx[(size_t)r0 * Nc + ccol]);
                float2 t1 = *reinterpret_cast<const float2*>(&g_tx[(size_t)(r0 + 8) * Nc + ccol]);
                o0.x += t0.x; o0.y += t0.y; o1.x += t1.x; o1.y += t1.y;
            }
            *reinterpret_cast<float2*>(&C[(size_t)r0 * Nc + ccol]) = o0;
            *reinterpret_cast<float2*>(&C[(size_t)(r0 + 8) * Nc + ccol]) = o1;
        }
    }
}

// ---- tx = LN(rep)+concat(x1,x2) (f32)  AND  y = LN(tx) split bf16 ----------
__global__ void txy_kernel(const float* __restrict__ x1, const float* __restrict__ x2,
                           const float* __restrict__ ag, const float* __restrict__ ab,
                           const float* __restrict__ g2, const float* __restrict__ b2) {
    int gw = (blockIdx.x * blockDim.x + threadIdx.x) >> 5;
    int lane = threadIdx.x & 31;
    if (gw >= BN) return;
    const float4* rr = reinterpret_cast<const float4*>(g_rep) + (size_t)gw * 64;
    float4 v[2];
    float s = 0.f, ss = 0.f;
#pragma unroll
    for (int i = 0; i < 2; i++) {
        v[i] = rr[i * 32 + lane];
        s  += v[i].x + v[i].y + v[i].z + v[i].w;
        ss += v[i].x * v[i].x + v[i].y * v[i].y + v[i].z * v[i].z + v[i].w * v[i].w;
    }
#pragma unroll
    for (int o = 16; o > 0; o >>= 1) {
        s  += __shfl_xor_sync(0xffffffffu, s, o);
        ss += __shfl_xor_sync(0xffffffffu, ss, o);
    }
    float mean = s * (1.0f / D2);
    float rstd = rsqrtf(ss * (1.0f / D2) - mean * mean + EPSLN);

    const float4* g4 = reinterpret_cast<const float4*>(ag);
    const float4* b4 = reinterpret_cast<const float4*>(ab);
    const float4* x14 = reinterpret_cast<const float4*>(x1) + (size_t)gw * 32;
    const float4* x24 = reinterpret_cast<const float4*>(x2) + (size_t)gw * 32;
    float4* txr = reinterpret_cast<float4*>(g_tx) + (size_t)gw * 64;

    float4 tv[2];
    float s2 = 0.f, ss2 = 0.f;
#pragma unroll
    for (int i = 0; i < 2; i++) {
        int c4 = i * 32 + lane;
        float4 gv = g4[c4], bv = b4[c4];
        float4 cat = (i == 0) ? x14[lane] : x24[lane];
        float4 r;
        r.x = (v[i].x - mean) * rstd * gv.x + bv.x + cat.x;
        r.y = (v[i].y - mean) * rstd * gv.y + bv.y + cat.y;
        r.z = (v[i].z - mean) * rstd * gv.z + bv.z + cat.z;
        r.w = (v[i].w - mean) * rstd * gv.w + bv.w + cat.w;
        txr[c4] = r;
        tv[i] = r;
        s2  += r.x + r.y + r.z + r.w;
        ss2 += r.x * r.x + r.y * r.y + r.z * r.z + r.w * r.w;
    }
#pragma unroll
    for (int o = 16; o > 0; o >>= 1) {
        s2  += __shfl_xor_sync(0xffffffffu, s2, o);
        ss2 += __shfl_xor_sync(0xffffffffu, ss2, o);
    }
    float mean2 = s2 * (1.0f / D2);
    float rstd2 = rsqrtf(ss2 * (1.0f / D2) - mean2 * mean2 + EPSLN);

    const float4* g24 = reinterpret_cast<const float4*>(g2);
    const float4* b24 = reinterpret_cast<const float4*>(b2);
#pragma unroll
    for (int i = 0; i < 2; i++) {
        int c4 = i * 32 + lane;
        float4 gv = g24[c4], bv = b24[c4], r;
        r.x = (tv[i].x - mean2) * rstd2 * gv.x + bv.x;
        r.y = (tv[i].y - mean2) * rstd2 * gv.y + bv.y;
        r.z = (tv[i].z - mean2) * rstd2 * gv.z + bv.z;
        r.w = (tv[i].w - mean2) * rstd2 * gv.w + bv.w;
        uint2 hp, lp;
        split4(r, hp, lp);
        size_t idx = (size_t)gw * D2 + c4 * 4;
        *reinterpret_cast<uint2*>(&g_yhi[idx]) = hp;
        *reinterpret_cast<uint2*>(&g_ylo[idx]) = lp;
    }
}

// ---- dwconv + bias + h1, then LN + GELU, write ax split bf16 ---------------
__global__ void dwlngelu_kernel(const float* __restrict__ dwb,
                                const float* __restrict__ mg,
                                const float* __restrict__ mb) {
    __shared__ float red[8];
    int n = blockIdx.x;
    int loc = n & (NN - 1);
    int m_ = loc & 15, w_ = (loc >> 4) & 31, h_ = loc >> 9;
    int tc = threadIdx.x;
    int lane = tc & 31, wrp = tc >> 5;
    const float4* x4 = reinterpret_cast<const float4*>(g_h1);

    float4 acc = x4[(size_t)n * 128 + tc];
    float4 bv = reinterpret_cast<const float4*>(dwb)[tc];
    acc.x += bv.x; acc.y += bv.y; acc.z += bv.z; acc.w += bv.w;

#pragma unroll
    for (int di = -1; di <= 1; di++) {
        int hh = h_ + di;
        if (hh < 0 || hh >= HH_) continue;
#pragma unroll
        for (int dj = -1; dj <= 1; dj++) {
            int ww = w_ + dj;
            if (ww < 0 || ww >= WW_) continue;
#pragma unroll
            for (int dk = -1; dk <= 1; dk++) {
                int mm = m_ + dk;
                if (mm < 0 || mm >= MM_) continue;
                int nn = n + di * (WW_ * MM_) + dj * MM_ + dk;
                float4 xv = x4[(size_t)nn * 128 + tc];
                float4 wt = reinterpret_cast<const float4*>(
                    g_dwT)[((di + 1) * 9 + (dj + 1) * 3 + (dk + 1)) * 128 + tc];
                acc.x += xv.x * wt.x; acc.y += xv.y * wt.y;
                acc.z += xv.z * wt.z; acc.w += xv.w * wt.w;
            }
        }
    }

    // block LN over 512 channels
    float s = acc.x + acc.y + acc.z + acc.w;
    float ss = acc.x * acc.x + acc.y * acc.y + acc.z * acc.z + acc.w * acc.w;
#pragma unroll
    for (int o = 16; o > 0; o >>= 1) {
        s  += __shfl_xor_sync(0xffffffffu, s, o);
        ss += __shfl_xor_sync(0xffffffffu, ss, o);
    }
    if (lane == 0) { red[wrp] = s; red[4 + wrp] = ss; }
    __syncthreads();
    s = red[0] + red[1] + red[2] + red[3];
    ss = red[4] + red[5] + red[6] + red[7];
    float mean = s * (1.0f / D4);
    float rstd = rsqrtf(ss * (1.0f / D4) - mean * mean + EPSLN);

    float4 gv = reinterpret_cast<const float4*>(mg)[tc];
    float4 b2 = reinterpret_cast<const float4*>(mb)[tc];
    float4 r;
    float t;
    t = (acc.x - mean) * rstd * gv.x + b2.x; r.x = t * normcdff(t);
    t = (acc.y - mean) * rstd * gv.y + b2.y; r.y = t * normcdff(t);
    t = (acc.z - mean) * rstd * gv.z + b2.z; r.z = t * normcdff(t);
    t = (acc.w - mean) * rstd * gv.w + b2.w; r.w = t * normcdff(t);

    uint2 hp, lp;
    split4(r, hp, lp);
    size_t idx = (size_t)n * D4 + tc * 4;
    *reinterpret_cast<uint2*>(&g_axhi[idx]) = hp;
    *reinterpret_cast<uint2*>(&g_axlo[idx]) = lp;
}

// ---------------------------------------------------------------------------
extern "C" void kernel_launch(void* const* d_in, const int* in_sizes, int n_in,
                              void* d_out, int out_size) {
    const float* x1    = (const float*)d_in[0];
    const float* x2    = (const float*)d_in[1];
    const float* ln1_g = (const float*)d_in[2];
    const float* ln1_b = (const float*)d_in[3];
    const float* rep_w = (const float*)d_in[4];
    const float* rep_b = (const float*)d_in[5];
    const float* aln_g = (const float*)d_in[6];
    const float* aln_b = (const float*)d_in[7];
    const float* ln2_g = (const float*)d_in[8];
    const float* ln2_b = (const float*)d_in[9];
    const float* fc1_w = (const float*)d_in[10];
    const float* fc1_b = (const float*)d_in[11];
    const float* dw_w  = (const float*)d_in[12];
    const float* dw_b  = (const float*)d_in[13];
    const float* mln_g = (const float*)d_in[14];
    const float* mln_b = (const float*)d_in[15];
    const float* fc2_w = (const float*)d_in[16];
    const float* fc2_b = (const float*)d_in[17];
    float* out = (float*)d_out;

    static int smem_set = 0;
    if (!smem_set) {
        cudaFuncSetAttribute(hgemm_kernel<0>, cudaFuncAttributeMaxDynamicSharedMemorySize, HSMEM_BYTES);
        cudaFuncSetAttribute(hgemm_kernel<1>, cudaFuncAttributeMaxDynamicSharedMemorySize, HSMEM_BYTES);
        cudaFuncSetAttribute(hgemm_kernel<2>, cudaFuncAttributeMaxDynamicSharedMemorySize, HSMEM_BYTES);
        smem_set = 1;
    }

    // norm1 on both streams
    ln_kernel<0><<<BN / 8, 256>>>(x1, ln1_g, ln1_b);
    ln_kernel<1><<<BN / 8, 256>>>(x2, ln1_g, ln1_b);
    prep_weights<<<512, 256>>>(rep_w, dw_w, fc1_w, fc2_w);

    // linear attention
    colstats_kernel<<<BB * CSPLIT, 128>>>();
    colcombine_kernel<<<BB, 128>>>();
    ctx_kernel<<<BB * NHEADS * 32, 1024>>>();
    ctx_reduce_kernel<<<16, 1024>>>();
    attq_kernel<<<BN / 32, 128>>>();

    // reprojection GEMM -> rep, then tx (f32) + y (bf16 split)
    hgemm_kernel<0><<<dim3(2, BN / 128), 256, HSMEM_BYTES>>>(rep_b, nullptr);
    txy_kernel<<<BN / 8, 256>>>(x1, x2, aln_g, aln_b, ln2_g, ln2_b);

    // MixFFN
    hgemm_kernel<1><<<dim3(4, BN / 128), 256, HSMEM_BYTES>>>(fc1_b, nullptr);
    dwlngelu_kernel<<<BN, 128>>>(dw_b, mln_g, mln_b);
    hgemm_kernel<2><<<dim3(2, BN / 128), 256, HSMEM_BYTES>>>(fc2_b, out);
}

// round 12
// speedup vs baseline: 1.0253x; 1.0023x over previous
#include <cuda_runtime.h>
#include <cuda_bf16.h>
#include <math.h>
#include <stdint.h>

#define BB     4
#define HH_    32
#define WW_    32
#define MM_    16
#define DD     128
#define NN     16384          // H*W*M
#define BN     65536          // B*N
#define D2     256
#define D4     512
#define NHEADS 4
#define HK     32
#define EPSLN  1e-5f
#define CSPLIT 256

// ---------------- scratch (device globals; no allocation allowed) ----------
__device__ __align__(16) float g_n1[BN * DD];
__device__ __align__(16) float g_n2[BN * DD];
__device__ __align__(16) float g_pmax[BB * CSPLIT * DD];
__device__ __align__(16) float g_psum[BB * CSPLIT * DD];
__device__ __align__(16) float g_cmax[BB * DD];
__device__ __align__(16) float g_cinv[BB * DD];
__device__ __align__(16) float g_ctxp[32 * BB * NHEADS * HK * HK];
__device__ __align__(16) float g_ctx[BB * NHEADS * HK * HK];
__device__ __align__(16) float g_rep[BN * D2];
__device__ __align__(16) float g_tx[BN * D2];
__device__ __align__(16) float g_h1[(size_t)BN * D4];
__device__ __align__(16) float g_dwT[27 * D4];
// pre-split bf16 GEMM A operands
__device__ __align__(16) __nv_bfloat16 g_agghi[BN * DD],        g_agglo[BN * DD];
__device__ __align__(16) __nv_bfloat16 g_yhi[BN * D2],          g_ylo[BN * D2];
__device__ __align__(16) __nv_bfloat16 g_axhi[(size_t)BN * D4], g_axlo[(size_t)BN * D4];
// pre-split bf16 weights, [N][K] K-major
__device__ __align__(16) __nv_bfloat16 g_w0hi[D2 * DD], g_w0lo[D2 * DD];   // rep
__device__ __align__(16) __nv_bfloat16 g_w1hi[D4 * D2], g_w1lo[D4 * D2];   // fc1
__device__ __align__(16) __nv_bfloat16 g_w2hi[D2 * D4], g_w2lo[D2 * D4];   // fc2

// ---------------- helpers ---------------------------------------------------
// NOTE: not volatile — dependencies are fully expressed via register
// constraints, letting ptxas interleave independent HMMAs and LDSMs.
__device__ __forceinline__ void mma16816(float* c, const uint32_t* a, const uint32_t* b) {
    asm("mma.sync.aligned.m16n8k16.row.col.f32.bf16.bf16.f32 "
        "{%0,%1,%2,%3}, {%4,%5,%6,%7}, {%8,%9}, {%0,%1,%2,%3};"
        : "+f"(c[0]), "+f"(c[1]), "+f"(c[2]), "+f"(c[3])
        : "r"(a[0]), "r"(a[1]), "r"(a[2]), "r"(a[3]), "r"(b[0]), "r"(b[1]));
}
__device__ __forceinline__ uint32_t smem_u32(const void* p) {
    uint32_t a;
    asm("{ .reg .u64 t; cvta.to.shared.u64 t, %1; cvt.u32.u64 %0, t; }" : "=r"(a) : "l"(p));
    return a;
}
__device__ __forceinline__ void ldsm_x4(uint32_t* r, uint32_t addr) {
    asm volatile("ldmatrix.sync.aligned.m8n8.x4.shared.b16 {%0,%1,%2,%3}, [%4];"
                 : "=r"(r[0]), "=r"(r[1]), "=r"(r[2]), "=r"(r[3]) : "r"(addr));
}
__device__ __forceinline__ void split_bf16(float v, uint16_t& hb, uint16_t& lb) {
    __nv_bfloat16 h = __float2bfloat16(v);
    __nv_bfloat16 l = __float2bfloat16(v - __bfloat162float(h));
    hb = __bfloat16_as_ushort(h);
    lb = __bfloat16_as_ushort(l);
}
// split a float4 and pack into uint2 (4 bf16)
__device__ __forceinline__ void split4(float4 v, uint2& hp, uint2& lp) {
    uint16_t hh[4], ll[4];
    split_bf16(v.x, hh[0], ll[0]);
    split_bf16(v.y, hh[1], ll[1]);
    split_bf16(v.z, hh[2], ll[2]);
    split_bf16(v.w, hh[3], ll[3]);
    hp.x = (uint32_t)hh[0] | ((uint32_t)hh[1] << 16);
    hp.y = (uint32_t)hh[2] | ((uint32_t)hh[3] << 16);
    lp.x = (uint32_t)ll[0] | ((uint32_t)ll[1] << 16);
    lp.y = (uint32_t)ll[2] | ((uint32_t)ll[3] << 16);
}

// ---------------- LayerNorm: one warp per row, float4 ----------------------
template <int MODE>
__global__ void ln_kernel(const float* __restrict__ x,
                          const float* __restrict__ gg,
                          const float* __restrict__ bb) {
    int gw = (blockIdx.x * blockDim.x + threadIdx.x) >> 5;
    int lane = threadIdx.x & 31;
    if (gw >= BN) return;
    float* dst = (MODE == 0) ? g_n1 : g_n2;

    const float4* xr = reinterpret_cast<const float4*>(x) + (size_t)gw * 32;
    float4 v = xr[lane];
    float s = v.x + v.y + v.z + v.w;
    float ss = v.x * v.x + v.y * v.y + v.z * v.z + v.w * v.w;
#pragma unroll
    for (int o = 16; o > 0; o >>= 1) {
        s  += __shfl_xor_sync(0xffffffffu, s, o);
        ss += __shfl_xor_sync(0xffffffffu, ss, o);
    }
    float mean = s * (1.0f / DD);
    float rstd = rsqrtf(ss * (1.0f / DD) - mean * mean + EPSLN);

    float4 gv = reinterpret_cast<const float4*>(gg)[lane];
    float4 bv = reinterpret_cast<const float4*>(bb)[lane];
    float4 r;
    r.x = (v.x - mean) * rstd * gv.x + bv.x;
    r.y = (v.y - mean) * rstd * gv.y + bv.y;
    r.z = (v.z - mean) * rstd * gv.z + bv.z;
    r.w = (v.w - mean) * rstd * gv.w + bv.w;
    reinterpret_cast<float4*>(dst)[(size_t)gw * 32 + lane] = r;
}

// ---------------- key softmax column stats over N (partials) --------------
__global__ void colstats_kernel() {
    int b = blockIdx.x >> 8, sp = blockIdx.x & (CSPLIT - 1);
    int d = threadIdx.x;
    const float* p = g_n2 + ((size_t)b * NN + sp * (NN / CSPLIT)) * DD + d;
    float m = -1e30f, s = 0.f;
    for (int i = 0; i < NN / CSPLIT; i++) {
        float v = p[(size_t)i * DD];
        float nm = fmaxf(m, v);
        s = s * __expf(m - nm) + __expf(v - nm);
        m = nm;
    }
    g_pmax[blockIdx.x * DD + d] = m;
    g_psum[blockIdx.x * DD + d] = s;
}

__global__ void colcombine_kernel() {
    int b = blockIdx.x, d = threadIdx.x;
    float m = -1e30f, s = 0.f;
    for (int sp = 0; sp < CSPLIT; sp++) {
        float pm = g_pmax[(b * CSPLIT + sp) * DD + d];
        float ps = g_psum[(b * CSPLIT + sp) * DD + d];
        float nm = fmaxf(m, pm);
        s = s * __expf(m - nm) + ps * __expf(pm - nm);
        m = nm;
    }
    g_cmax[b * DD + d] = m;
    g_cinv[b * DD + d] = 1.0f / s;
}

// ---------------- context[b,h,k,v] = sum_n key * v   (split-N partials) ---
__global__ void ctx_kernel() {
    int sp = blockIdx.x & 31;
    int h  = (blockIdx.x >> 5) & 3;
    int b  = blockIdx.x >> 7;
    int tid = threadIdx.x;
    int v = tid & 31, k = tid >> 5;

    __shared__ float cm[HK], ci[HK];
    __shared__ float ke[16][HK], vv[16][HK];
    if (tid < HK) {
        cm[tid] = g_cmax[b * DD + h * HK + tid];
        ci[tid] = g_cinv[b * DD + h * HK + tid];
    }
    float acc = 0.f;
    int n0 = sp * 512;
    int tt = tid >> 6, col = tid & 63;
    for (int t0 = 0; t0 < 512; t0 += 16) {
        __syncthreads();
        int n = n0 + t0 + tt;
        size_t base = ((size_t)b * NN + n) * DD + h * HK;
        if (col < HK) ke[tt][col] = __expf(g_n2[base + col] - cm[col]) * ci[col];
        else          vv[tt][col - HK] = g_n1[base + col - HK];
        __syncthreads();
#pragma unroll
        for (int t = 0; t < 16; t++) acc += ke[t][k] * vv[t][v];
    }
    g_ctxp[(size_t)sp * (BB * NHEADS * HK * HK) +
           (((b * NHEADS + h) * HK + k) * HK + v)] = acc;
}

__global__ void ctx_reduce_kernel() {
    int i = blockIdx.x * 1024 + threadIdx.x;
    float s = 0.f;
    for (int sp = 0; sp < 32; sp++) s += g_ctxp[sp * (BB * NHEADS * HK * HK) + i];
    g_ctx[i] = s;
}

// ---------------- weight re-layouts + bf16 splits ---------------------------
__global__ void prep_weights(const float* __restrict__ rep_w,
                             const float* __restrict__ dw_w,
                             const float* __restrict__ fc1_w,
                             const float* __restrict__ fc2_w) {
    int i = blockIdx.x * 256 + threadIdx.x;
    uint16_t hb, lb;
    if (i < D2 * DD) {                      // rep_w already [N=256][K=128]
        split_bf16(rep_w[i], hb, lb);
        g_w0hi[i] = __ushort_as_bfloat16(hb); g_w0lo[i] = __ushort_as_bfloat16(lb);
    }
    if (i < D4 * D2) {                      // fc1_w [K=256][N=512] -> [n][k]
        int n = i >> 8, k = i & 255;
        split_bf16(fc1_w[k * D4 + n], hb, lb);
        g_w1hi[i] = __ushort_as_bfloat16(hb); g_w1lo[i] = __ushort_as_bfloat16(lb);
    }
    if (i < D2 * D4) {                      // fc2_w [K=512][N=256] -> [n][k]
        int n = i >> 9, k = i & 511;
        split_bf16(fc2_w[k * D2 + n], hb, lb);
        g_w2hi[i] = __ushort_as_bfloat16(hb); g_w2lo[i] = __ushort_as_bfloat16(lb);
    }
    if (i < 27 * D4) {                      // dw_w [c][27] -> [tap][c]
        int c = i / 27, t = i % 27;
        g_dwT[t * D4 + c] = dw_w[i];
    }
}

// ---------------- query softmax + att matvec -> agg (split bf16) ----------
__global__ void attq_kernel() {
    __shared__ float sn2[32][129];
    __shared__ float sctx[NHEADS][HK][HK];
    int b = blockIdx.x >> 9;
    int tok0 = (blockIdx.x & 511) * 32;
    int tid = threadIdx.x;

    for (int i = tid; i < NHEADS * HK * HK; i += 128)
        ((float*)sctx)[i] = g_ctx[b * (NHEADS * HK * HK) + i];
    for (int i = tid; i < 32 * 128; i += 128) {
        int r = i >> 7, c = i & 127;
        sn2[r][c] = g_n2[((size_t)b * NN + tok0 + r) * DD + c];
    }
    __syncthreads();

    int h = tid >> 5, t = tid & 31;
    float q[HK];
    float mx = -1e30f;
#pragma unroll
    for (int k = 0; k < HK; k++) { q[k] = sn2[t][h * HK + k]; mx = fmaxf(mx, q[k]); }
    float sum = 0.f;
#pragma unroll
    for (int k = 0; k < HK; k++) { q[k] = __expf(q[k] - mx); sum += q[k]; }
    float inv = 1.0f / sum;

    float av[HK];
#pragma unroll
    for (int j = 0; j < HK; j++) av[j] = 0.f;
#pragma unroll
    for (int k = 0; k < HK; k++) {
        float qk = q[k] * inv;
#pragma unroll
        for (int j = 0; j < HK; j++) av[j] += qk * sctx[h][k][j];
    }
    __syncthreads();
#pragma unroll
    for (int j = 0; j < HK; j++) sn2[t][h * HK + j] = av[j];
    __syncthreads();
    // scalar LDS reads (row stride 129 floats is not 16B-aligned)
    for (int i = tid; i < 32 * 32; i += 128) {
        int r = i >> 5, c4 = i & 31;
        float4 v;
        v.x = sn2[r][c4 * 4 + 0];
        v.y = sn2[r][c4 * 4 + 1];
        v.z = sn2[r][c4 * 4 + 2];
        v.w = sn2[r][c4 * 4 + 3];
        uint2 hp, lp;
        split4(v, hp, lp);
        size_t idx = ((size_t)b * NN + tok0 + r) * DD + c4 * 4;
        *reinterpret_cast<uint2*>(&g_agghi[idx]) = hp;
        *reinterpret_cast<uint2*>(&g_agglo[idx]) = lp;
    }
}

// ---------------- HMMA bf16 3-term split GEMM (ldmatrix fragments) ----------
// WHICH 0: agg[65536,128] @ w0[256,128]^T            -> g_rep
// WHICH 1: y  [65536,256] @ w1[512,256]^T            -> g_h1
// WHICH 2: ax [65536,512] @ w2[256,512]^T + b + tx   -> Cout (d_out)
// CTA tile 128x128, BK=32, 8 warps (4m x 2n), warp tile 32x64.
#define LDKP 40                      // padded bf16 k-stride (80B rows: LDSM conflict-free)
#define ATILE (128 * LDKP)           // elems per matrix per stage
#define HSMEM_BYTES (8 * ATILE * 2)  // 4 matrices x 2 stages = 81920 B

template <int WHICH>
__global__ void __launch_bounds__(256) hgemm_kernel(const float* __restrict__ bias,
                                                    float* __restrict__ CoutP) {
    constexpr int K  = (WHICH == 0) ? 128 : (WHICH == 1) ? 256 : 512;
    constexpr int Nc = (WHICH == 1) ? 512 : 256;
    constexpr int CHUNKS = K / 32;

    const __nv_bfloat16* Ah = (WHICH == 0) ? g_agghi : (WHICH == 1) ? g_yhi : g_axhi;
    const __nv_bfloat16* Al = (WHICH == 0) ? g_agglo : (WHICH == 1) ? g_ylo : g_axlo;
    const __nv_bfloat16* Bh = (WHICH == 0) ? g_w0hi : (WHICH == 1) ? g_w1hi : g_w2hi;
    const __nv_bfloat16* Bl = (WHICH == 0) ? g_w0lo : (WHICH == 1) ? g_w1lo : g_w2lo;
    float* C = (WHICH == 0) ? g_rep : (WHICH == 1) ? g_h1 : CoutP;

    extern __shared__ __align__(16) __nv_bfloat16 sm_bf[];
    __nv_bfloat16* sAh = sm_bf;               // [2][ATILE]
    __nv_bfloat16* sAl = sAh + 2 * ATILE;
    __nv_bfloat16* sBh = sAl + 2 * ATILE;
    __nv_bfloat16* sBl = sBh + 2 * ATILE;

    int tid = threadIdx.x, lane = tid & 31, wid = tid >> 5;
    int wm = wid >> 1, wn = wid & 1;
    int m0 = blockIdx.y * 128, n0 = blockIdx.x * 128;
    int g = lane >> 2, t4 = lane & 3;

    int ar_ = tid >> 2, aq_ = tid & 3;  // A loader: row ar_+64i, uint4-col aq_ (8 bf16)
    int bn = tid >> 2, bq = tid & 3;    // B loader: row bn+64i, uint4-col bq

    // ldmatrix per-lane element offsets (in bf16 elems, relative to stage base)
    int a_row = wm * 32 + (lane & 15);
    int a_elem = a_row * LDKP + (lane >> 4) * 8;
    int b_row = wn * 64 + (lane & 7) + ((lane >> 4) << 3);
    int b_elem = b_row * LDKP + ((lane >> 3) & 1) * 8;

    uint32_t sAh_u = smem_u32(sAh), sAl_u = smem_u32(sAl);
    uint32_t sBh_u = smem_u32(sBh), sBl_u = smem_u32(sBl);

    uint4 ahr[2], alr[2], bhr[2], blr[2];
    float acc[2][8][4] = {};

    // ---- prologue: LDG chunk 0
#pragma unroll
    for (int i = 0; i < 2; i++) {
        size_t aoff = (size_t)(m0 + ar_ + 64 * i) * K + aq_ * 8;
        ahr[i] = *reinterpret_cast<const uint4*>(Ah + aoff);
        alr[i] = *reinterpret_cast<const uint4*>(Al + aoff);
        size_t boff = (size_t)(n0 + bn + 64 * i) * K + bq * 8;
        bhr[i] = *reinterpret_cast<const uint4*>(Bh + boff);
        blr[i] = *reinterpret_cast<const uint4*>(Bl + boff);
    }
    // STS stage 0
#pragma unroll
    for (int i = 0; i < 2; i++) {
        int ra = ar_ + 64 * i, rb = bn + 64 * i;
        *reinterpret_cast<uint4*>(sAh + ra * LDKP + aq_ * 8) = ahr[i];
        *reinterpret_cast<uint4*>(sAl + ra * LDKP + aq_ * 8) = alr[i];
        *reinterpret_cast<uint4*>(sBh + rb * LDKP + bq * 8) = bhr[i];
        *reinterpret_cast<uint4*>(sBl + rb * LDKP + bq * 8) = blr[i];
    }
    __syncthreads();

    for (int c = 0; c < CHUNKS; c++) {
        int s = c & 1;
        if (c + 1 < CHUNKS) {  // prefetch next chunk
            int k0 = (c + 1) * 32;
#pragma unroll
            for (int i = 0; i < 2; i++) {
                size_t aoff = (size_t)(m0 + ar_ + 64 * i) * K + k0 + aq_ * 8;
                ahr[i] = *reinterpret_cast<const uint4*>(Ah + aoff);
                alr[i] = *reinterpret_cast<const uint4*>(Al + aoff);
                size_t boff = (size_t)(n0 + bn + 64 * i) * K + k0 + bq * 8;
                bhr[i] = *reinterpret_cast<const uint4*>(Bh + boff);
                blr[i] = *reinterpret_cast<const uint4*>(Bl + boff);
            }
        }
        uint32_t stg = (uint32_t)(s * ATILE * 2);  // stage byte offset

#pragma unroll
        for (int kk = 0; kk < 32; kk += 16) {
            uint32_t ah[2][4], al[2][4], bh[8][2], bl[8][2];
            uint32_t a_base = stg + (uint32_t)(a_elem + kk) * 2;
            uint32_t b_base = stg + (uint32_t)(b_elem + kk) * 2;
#pragma unroll
            for (int mt = 0; mt < 2; mt++) {
                uint32_t off = a_base + (uint32_t)(mt * 16 * LDKP) * 2;
                ldsm_x4(ah[mt], sAh_u + off);
                ldsm_x4(al[mt], sAl_u + off);
            }
#pragma unroll
            for (int p = 0; p < 4; p++) {
                uint32_t off = b_base + (uint32_t)(p * 16 * LDKP) * 2;
                uint32_t th[4], tl[4];
                ldsm_x4(th, sBh_u + off);
                ldsm_x4(tl, sBl_u + off);
                bh[2 * p][0] = th[0]; bh[2 * p][1] = th[1];
                bh[2 * p + 1][0] = th[2]; bh[2 * p + 1][1] = th[3];
                bl[2 * p][0] = tl[0]; bl[2 * p][1] = tl[1];
                bl[2 * p + 1][0] = tl[2]; bl[2 * p + 1][1] = tl[3];
            }
            // term-major order: consecutive MMAs hit 16 DISTINCT accumulators,
            // so same-acc reuse is 16 issues apart (covers HMMA latency).
#pragma unroll
            for (int mt = 0; mt < 2; mt++)
#pragma unroll
                for (int nt = 0; nt < 8; nt++)
                    mma16816(acc[mt][nt], ah[mt], bh[nt]);
#pragma unroll
            for (int mt = 0; mt < 2; mt++)
#pragma unroll
                for (int nt = 0; nt < 8; nt++)
                    mma16816(acc[mt][nt], al[mt], bh[nt]);
#pragma unroll
            for (int mt = 0; mt < 2; mt++)
#pragma unroll
                for (int nt = 0; nt < 8; nt++)
                    mma16816(acc[mt][nt], ah[mt], bl[nt]);
        }

        if (c + 1 < CHUNKS) {  // STS next stage
            int s1 = (c + 1) & 1;
#pragma unroll
            for (int i = 0; i < 2; i++) {
                int ra = ar_ + 64 * i, rb = bn + 64 * i;
                *reinterpret_cast<uint4*>(sAh + s1 * ATILE + ra * LDKP + aq_ * 8) = ahr[i];
                *reinterpret_cast<uint4*>(sAl + s1 * ATILE + ra * LDKP + aq_ * 8) = alr[i];
                *reinterpret_cast<uint4*>(sBh + s1 * ATILE + rb * LDKP + bq * 8) = bhr[i];
                *reinterpret_cast<uint4*>(sBl + s1 * ATILE + rb * LDKP + bq * 8) = blr[i];
            }
        }
        __syncthreads();
    }

    // ---- epilogue
#pragma unroll
    for (int mt = 0; mt < 2; mt++) {
        int r0 = m0 + wm * 32 + mt * 16 + g;
#pragma unroll
        for (int nt = 0; nt < 8; nt++) {
            int ccol = n0 + wn * 64 + nt * 8 + t4 * 2;
            float2 bv = *reinterpret_cast<const float2*>(bias + ccol);
            float2 o0, o1;
            o0.x = acc[mt][nt][0] + bv.x; o0.y = acc[mt][nt][1] + bv.y;
            o1.x = acc[mt][nt][2] + bv.x; o1.y = acc[mt][nt][3] + bv.y;
            if (WHICH == 2) {
                float2 t0 = *reinterpret_cast<const float2*>(&g_tx[(size_t)r0 * Nc + ccol]);
                float2 t1 = *reinterpret_cast<const float2*>(&g_tx[(size_t)(r0 + 8) * Nc + ccol]);
                o0.x += t0.x; o0.y += t0.y; o1.x += t1.x; o1.y += t1.y;
            }
            *reinterpret_cast<float2*>(&C[(size_t)r0 * Nc + ccol]) = o0;
            *reinterpret_cast<float2*>(&C[(size_t)(r0 + 8) * Nc + ccol]) = o1;
        }
    }
}

// ---- tx = LN(rep)+concat(x1,x2) (f32)  AND  y = LN(tx) split bf16 ----------
__global__ void txy_kernel(const float* __restrict__ x1, const float* __restrict__ x2,
                           const float* __restrict__ ag, const float* __restrict__ ab,
                           const float* __restrict__ g2, const float* __restrict__ b2) {
    int gw = (blockIdx.x * blockDim.x + threadIdx.x) >> 5;
    int lane = threadIdx.x & 31;
    if (gw >= BN) return;
    const float4* rr = reinterpret_cast<const float4*>(g_rep) + (size_t)gw * 64;
    float4 v[2];
    float s = 0.f, ss = 0.f;
#pragma unroll
    for (int i = 0; i < 2; i++) {
        v[i] = rr[i * 32 + lane];
        s  += v[i].x + v[i].y + v[i].z + v[i].w;
        ss += v[i].x * v[i].x + v[i].y * v[i].y + v[i].z * v[i].z + v[i].w * v[i].w;
    }
#pragma unroll
    for (int o = 16; o > 0; o >>= 1) {
        s  += __shfl_xor_sync(0xffffffffu, s, o);
        ss += __shfl_xor_sync(0xffffffffu, ss, o);
    }
    float mean = s * (1.0f / D2);
    float rstd = rsqrtf(ss * (1.0f / D2) - mean * mean + EPSLN);

    const float4* g4 = reinterpret_cast<const float4*>(ag);
    const float4* b4 = reinterpret_cast<const float4*>(ab);
    const float4* x14 = reinterpret_cast<const float4*>(x1) + (size_t)gw * 32;
    const float4* x24 = reinterpret_cast<const float4*>(x2) + (size_t)gw * 32;
    float4* txr = reinterpret_cast<float4*>(g_tx) + (size_t)gw * 64;

    float4 tv[2];
    float s2 = 0.f, ss2 = 0.f;
#pragma unroll
    for (int i = 0; i < 2; i++) {
        int c4 = i * 32 + lane;
        float4 gv = g4[c4], bv = b4[c4];
        float4 cat = (i == 0) ? x14[lane] : x24[lane];
        float4 r;
        r.x = (v[i].x - mean) * rstd * gv.x + bv.x + cat.x;
        r.y = (v[i].y - mean) * rstd * gv.y + bv.y + cat.y;
        r.z = (v[i].z - mean) * rstd * gv.z + bv.z + cat.z;
        r.w = (v[i].w - mean) * rstd * gv.w + bv.w + cat.w;
        txr[c4] = r;
        tv[i] = r;
        s2  += r.x + r.y + r.z + r.w;
        ss2 += r.x * r.x + r.y * r.y + r.z * r.z + r.w * r.w;
    }
#pragma unroll
    for (int o = 16; o > 0; o >>= 1) {
        s2  += __shfl_xor_sync(0xffffffffu, s2, o);
        ss2 += __shfl_xor_sync(0xffffffffu, ss2, o);
    }
    float mean2 = s2 * (1.0f / D2);
    float rstd2 = rsqrtf(ss2 * (1.0f / D2) - mean2 * mean2 + EPSLN);

    const float4* g24 = reinterpret_cast<const float4*>(g2);
    const float4* b24 = reinterpret_cast<const float4*>(b2);
#pragma unroll
    for (int i = 0; i < 2; i++) {
        int c4 = i * 32 + lane;
        float4 gv = g24[c4], bv = b24[c4], r;
        r.x = (tv[i].x - mean2) * rstd2 * gv.x + bv.x;
        r.y = (tv[i].y - mean2) * rstd2 * gv.y + bv.y;
        r.z = (tv[i].z - mean2) * rstd2 * gv.z + bv.z;
        r.w = (tv[i].w - mean2) * rstd2 * gv.w + bv.w;
        uint2 hp, lp;
        split4(r, hp, lp);
        size_t idx = (size_t)gw * D2 + c4 * 4;
        *reinterpret_cast<uint2*>(&g_yhi[idx]) = hp;
        *reinterpret_cast<uint2*>(&g_ylo[idx]) = lp;
    }
}

// ---- dwconv + bias + h1, then LN + GELU, write ax split bf16 ---------------
__global__ void dwlngelu_kernel(const float* __restrict__ dwb,
                                const float* __restrict__ mg,
                                const float* __restrict__ mb) {
    __shared__ float red[8];
    int n = blockIdx.x;
    int loc = n & (NN - 1);
    int m_ = loc & 15, w_ = (loc >> 4) & 31, h_ = loc >> 9;
    int tc = threadIdx.x;
    int lane = tc & 31, wrp = tc >> 5;
    const float4* x4 = reinterpret_cast<const float4*>(g_h1);

    float4 acc = x4[(size_t)n * 128 + tc];
    float4 bv = reinterpret_cast<const float4*>(dwb)[tc];
    acc.x += bv.x; acc.y += bv.y; acc.z += bv.z; acc.w += bv.w;

#pragma unroll
    for (int di = -1; di <= 1; di++) {
        int hh = h_ + di;
        if (hh < 0 || hh >= HH_) continue;
#pragma unroll
        for (int dj = -1; dj <= 1; dj++) {
            int ww = w_ + dj;
            if (ww < 0 || ww >= WW_) continue;
#pragma unroll
            for (int dk = -1; dk <= 1; dk++) {
                int mm = m_ + dk;
                if (mm < 0 || mm >= MM_) continue;
                int nn = n + di * (WW_ * MM_) + dj * MM_ + dk;
                float4 xv = x4[(size_t)nn * 128 + tc];
                float4 wt = reinterpret_cast<const float4*>(
                    g_dwT)[((di + 1) * 9 + (dj + 1) * 3 + (dk + 1)) * 128 + tc];
                acc.x += xv.x * wt.x; acc.y += xv.y * wt.y;
                acc.z += xv.z * wt.z; acc.w += xv.w * wt.w;
            }
        }
    }

    // block LN over 512 channels
    float s = acc.x + acc.y + acc.z + acc.w;
    float ss = acc.x * acc.x + acc.y * acc.y + acc.z * acc.z + acc.w * acc.w;
#pragma unroll
    for (int o = 16; o > 0; o >>= 1) {
        s  += __shfl_xor_sync(0xffffffffu, s, o);
        ss += __shfl_xor_sync(0xffffffffu, ss, o);
    }
    if (lane == 0) { red[wrp] = s; red[4 + wrp] = ss; }
    __syncthreads();
    s = red[0] + red[1] + red[2] + red[3];
    ss = red[4] + red[5] + red[6] + red[7];
    float mean = s * (1.0f / D4);
    float rstd = rsqrtf(ss * (1.0f / D4) - mean * mean + EPSLN);

    float4 gv = reinterpret_cast<const float4*>(mg)[tc];
    float4 b2 = reinterpret_cast<const float4*>(mb)[tc];
    float4 r;
    float t;
    t = (acc.x - mean) * rstd * gv.x + b2.x; r.x = t * normcdff(t);
    t = (acc.y - mean) * rstd * gv.y + b2.y; r.y = t * normcdff(t);
    t = (acc.z - mean) * rstd * gv.z + b2.z; r.z = t * normcdff(t);
    t = (acc.w - mean) * rstd * gv.w + b2.w; r.w = t * normcdff(t);

    uint2 hp, lp;
    split4(r, hp, lp);
    size_t idx = (size_t)n * D4 + tc * 4;
    *reinterpret_cast<uint2*>(&g_axhi[idx]) = hp;
    *reinterpret_cast<uint2*>(&g_axlo[idx]) = lp;
}

// ---------------------------------------------------------------------------
extern "C" void kernel_launch(void* const* d_in, const int* in_sizes, int n_in,
                              void* d_out, int out_size) {
    const float* x1    = (const float*)d_in[0];
    const float* x2    = (const float*)d_in[1];
    const float* ln1_g = (const float*)d_in[2];
    const float* ln1_b = (const float*)d_in[3];
    const float* rep_w = (const float*)d_in[4];
    const float* rep_b = (const float*)d_in[5];
    const float* aln_g = (const float*)d_in[6];
    const float* aln_b = (const float*)d_in[7];
    const float* ln2_g = (const float*)d_in[8];
    const float* ln2_b = (const float*)d_in[9];
    const float* fc1_w = (const float*)d_in[10];
    const float* fc1_b = (const float*)d_in[11];
    const float* dw_w  = (const float*)d_in[12];
    const float* dw_b  = (const float*)d_in[13];
    const float* mln_g = (const float*)d_in[14];
    const float* mln_b = (const float*)d_in[15];
    const float* fc2_w = (const float*)d_in[16];
    const float* fc2_b = (const float*)d_in[17];
    float* out = (float*)d_out;

    static int smem_set = 0;
    if (!smem_set) {
        cudaFuncSetAttribute(hgemm_kernel<0>, cudaFuncAttributeMaxDynamicSharedMemorySize, HSMEM_BYTES);
        cudaFuncSetAttribute(hgemm_kernel<1>, cudaFuncAttributeMaxDynamicSharedMemorySize, HSMEM_BYTES);
        cudaFuncSetAttribute(hgemm_kernel<2>, cudaFuncAttributeMaxDynamicSharedMemorySize, HSMEM_BYTES);
        smem_set = 1;
    }

    // norm1 on both streams
    ln_kernel<0><<<BN / 8, 256>>>(x1, ln1_g, ln1_b);
    ln_kernel<1><<<BN / 8, 256>>>(x2, ln1_g, ln1_b);
    prep_weights<<<512, 256>>>(rep_w, dw_w, fc1_w, fc2_w);

    // linear attention
    colstats_kernel<<<BB * CSPLIT, 128>>>();
    colcombine_kernel<<<BB, 128>>>();
    ctx_kernel<<<BB * NHEADS * 32, 1024>>>();
    ctx_reduce_kernel<<<16, 1024>>>();
    attq_kernel<<<BN / 32, 128>>>();

    // reprojection GEMM -> rep, then tx (f32) + y (bf16 split)
    hgemm_kernel<0><<<dim3(2, BN / 128), 256, HSMEM_BYTES>>>(rep_b, nullptr);
    txy_kernel<<<BN / 8, 256>>>(x1, x2, aln_g, aln_b, ln2_g, ln2_b);

    // MixFFN
    hgemm_kernel<1><<<dim3(4, BN / 128), 256, HSMEM_BYTES>>>(fc1_b, nullptr);
    dwlngelu_kernel<<<BN, 128>>>(dw_b, mln_g, mln_b);
    hgemm_kernel<2><<<dim3(2, BN / 128), 256, HSMEM_BYTES>>>(fc2_b, out);
}